// round 5
// baseline (speedup 1.0000x reference)
#include <cuda_runtime.h>
#include <cstdint>

#define MAXN 100000
#define MAXE 1600000
#define DIN  64

// ---------------- scratch (no cudaMalloc allowed) ----------------
__device__ float g_XE[(size_t)MAXN * 64];   // sum of e * X[src] per dst
__device__ float g_X1[(size_t)MAXN * 64];   // sum of X[src] per dst
__device__ float g_HA[(size_t)MAXN * 64];   // relu(layer1 out)
__device__ float g_HB[(size_t)MAXN * 64];   // relu(layer2 out)
__device__ int   g_counts[MAXN];
__device__ int   g_off[MAXN + 1];
__device__ int   g_cursor[MAXN];
__device__ int2  g_meta[MAXE];              // {src, bits(e)} grouped by dst

// =================================================================
// CSR build
// =================================================================
__global__ void hist_kernel(const int* __restrict__ ei, int* __restrict__ counts, int E)
{
    int e = blockIdx.x * blockDim.x + threadIdx.x;
    if (e < E) atomicAdd(&counts[__ldg(ei + E + e)], 1);
}

__global__ __launch_bounds__(1024) void scan_kernel(const int* __restrict__ counts,
                                                    int* __restrict__ off,
                                                    int* __restrict__ cursor, int N)
{
    __shared__ int ssum[1024];
    int tid = threadIdx.x;
    int chunk = (N + 1023) / 1024;
    int lo = tid * chunk;
    int hi = min(lo + chunk, N);
    int s = 0;
    for (int i = lo; i < hi; i++) s += counts[i];
    ssum[tid] = s;
    __syncthreads();
    for (int d = 1; d < 1024; d <<= 1) {
        int v = (tid >= d) ? ssum[tid - d] : 0;
        __syncthreads();
        ssum[tid] += v;
        __syncthreads();
    }
    int base = (tid == 0) ? 0 : ssum[tid - 1];
    for (int i = lo; i < hi; i++) {
        off[i] = base; cursor[i] = base;
        base += counts[i];
    }
    if (tid == 0) off[N] = ssum[1023];
}

__global__ void scatter_kernel(const int* __restrict__ ei, const float* __restrict__ ea,
                               int* __restrict__ cursor, int2* __restrict__ meta, int E)
{
    int e = blockIdx.x * blockDim.x + threadIdx.x;
    if (e >= E) return;
    int s = __ldg(ei + e);
    int d = __ldg(ei + E + e);
    int pos = atomicAdd(&cursor[d], 1);
    meta[pos] = make_int2(s, __float_as_int(__ldg(ea + e)));
}

// =================================================================
// Feature-space aggregation (R3 measured-best variant):
// one warp per node, lane owns 2 channels, unroll-2
// =================================================================
__global__ __launch_bounds__(256) void aggx_kernel(const int* __restrict__ off,
                                                   const int2* __restrict__ meta,
                                                   const float* __restrict__ X,
                                                   float* __restrict__ XE,
                                                   float* __restrict__ X1, int N)
{
    int w = (blockIdx.x * blockDim.x + threadIdx.x) >> 5;
    int lane = threadIdx.x & 31;
    if (w >= N) return;

    int beg = __ldg(off + w);
    int end = __ldg(off + w + 1);

    float2 aE = make_float2(0.f, 0.f);
    float2 a1 = make_float2(0.f, 0.f);

    int k = beg;
    for (; k + 2 <= end; k += 2) {
        int2 m0 = __ldg(meta + k);
        int2 m1 = __ldg(meta + k + 1);
        float2 v0 = *reinterpret_cast<const float2*>(X + (size_t)m0.x * 64 + lane * 2);
        float2 v1 = *reinterpret_cast<const float2*>(X + (size_t)m1.x * 64 + lane * 2);
        float e0 = __int_as_float(m0.y);
        float e1 = __int_as_float(m1.y);
        aE.x = fmaf(e0, v0.x, aE.x); aE.y = fmaf(e0, v0.y, aE.y);
        aE.x = fmaf(e1, v1.x, aE.x); aE.y = fmaf(e1, v1.y, aE.y);
        a1.x += v0.x + v1.x;         a1.y += v0.y + v1.y;
    }
    if (k < end) {
        int2 m0 = __ldg(meta + k);
        float2 v0 = *reinterpret_cast<const float2*>(X + (size_t)m0.x * 64 + lane * 2);
        float e0 = __int_as_float(m0.y);
        aE.x = fmaf(e0, v0.x, aE.x); aE.y = fmaf(e0, v0.y, aE.y);
        a1.x += v0.x;                a1.y += v0.y;
    }

    *reinterpret_cast<float2*>(XE + (size_t)w * 64 + lane * 2) = aE;
    *reinterpret_cast<float2*>(X1 + (size_t)w * 64 + lane * 2) = a1;
}

// =================================================================
// K=192 fused GEMM: H = relu?(XE@Wm + X1@Bm + X@Wr + b)
// 256 threads, 64-row tile, 1 col x 16 rows per thread.
// Inner loop: 1 distinct-w LDS + 4 broadcast LDS.128 per 16 FMA.
// =================================================================
#define TPAD 68
#define TILE_FLOATS (64 * TPAD)
#define G_SMEM_FLOATS (3 * TILE_FLOATS + 3 * 4096 + 64)
#define G_SMEM_BYTES  (G_SMEM_FLOATS * 4)

template<bool RELU>
__global__ __launch_bounds__(256) void gemm192(const float* __restrict__ XEp,
                                               const float* __restrict__ X1p,
                                               const float* __restrict__ Xp,
                                               const float* __restrict__ Wm,
                                               const float* __restrict__ Bm,
                                               const float* __restrict__ Wr,
                                               const float* __restrict__ bias,
                                               float* __restrict__ H, int N)
{
    extern __shared__ float sm[];
    float* sT = sm;                       // 3 tiles, [seg][k*TPAD + r]
    float* sW = sm + 3 * TILE_FLOATS;     // 3 weights, [seg][k*64 + c]
    float* sb = sW + 3 * 4096;

    const int tid = threadIdx.x;
    const int tx = tid & 63;              // output col
    const int ty = tid >> 6;              // 0..3, rows ty*16 .. +15
    const int row0 = blockIdx.x * 64;

    #pragma unroll
    for (int i = tid; i < 4096; i += 256) {
        sW[i]        = Wm[i];
        sW[4096 + i] = Bm[i];
        sW[8192 + i] = Wr[i];
    }
    if (tid < 64) sb[tid] = bias[tid];

    // stage 3 input tiles transposed (coalesced global reads)
    #pragma unroll
    for (int i = tid; i < 4096; i += 256) {
        int r = i >> 6;
        int k = i & 63;
        int row = row0 + r;
        bool ok = row < N;
        float v0 = ok ? XEp[(size_t)row * 64 + k] : 0.f;
        float v1 = ok ? X1p[(size_t)row * 64 + k] : 0.f;
        float v2 = ok ? Xp [(size_t)row * 64 + k] : 0.f;
        sT[                  k * TPAD + r] = v0;
        sT[    TILE_FLOATS + k * TPAD + r] = v1;
        sT[2 * TILE_FLOATS + k * TPAD + r] = v2;
    }
    __syncthreads();

    float acc[16];
    #pragma unroll
    for (int r = 0; r < 16; r++) acc[r] = 0.f;

    #pragma unroll
    for (int seg = 0; seg < 3; seg++) {
        const float* tile = sT + seg * TILE_FLOATS + ty * 16;
        const float* W    = sW + seg * 4096 + tx;
        #pragma unroll 4
        for (int k = 0; k < 64; k++) {
            float w = W[k * 64];
            const float* xr = tile + k * TPAD;
            float4 xa = *reinterpret_cast<const float4*>(xr);
            float4 xb = *reinterpret_cast<const float4*>(xr + 4);
            float4 xc = *reinterpret_cast<const float4*>(xr + 8);
            float4 xd = *reinterpret_cast<const float4*>(xr + 12);
            acc[ 0] = fmaf(xa.x, w, acc[ 0]);
            acc[ 1] = fmaf(xa.y, w, acc[ 1]);
            acc[ 2] = fmaf(xa.z, w, acc[ 2]);
            acc[ 3] = fmaf(xa.w, w, acc[ 3]);
            acc[ 4] = fmaf(xb.x, w, acc[ 4]);
            acc[ 5] = fmaf(xb.y, w, acc[ 5]);
            acc[ 6] = fmaf(xb.z, w, acc[ 6]);
            acc[ 7] = fmaf(xb.w, w, acc[ 7]);
            acc[ 8] = fmaf(xc.x, w, acc[ 8]);
            acc[ 9] = fmaf(xc.y, w, acc[ 9]);
            acc[10] = fmaf(xc.z, w, acc[10]);
            acc[11] = fmaf(xc.w, w, acc[11]);
            acc[12] = fmaf(xd.x, w, acc[12]);
            acc[13] = fmaf(xd.y, w, acc[13]);
            acc[14] = fmaf(xd.z, w, acc[14]);
            acc[15] = fmaf(xd.w, w, acc[15]);
        }
    }

    float b = sb[tx];
    #pragma unroll
    for (int r = 0; r < 16; r++) {
        int row = row0 + ty * 16 + r;
        if (row < N) {
            float v = acc[r] + b;
            if (RELU) v = fmaxf(v, 0.f);
            H[(size_t)row * 64 + tx] = v;
        }
    }
}

// =================================================================
// Layer 3 + log_softmax fused
// =================================================================
__global__ __launch_bounds__(256) void gemm3_ls(const float* __restrict__ XEp,
                                                const float* __restrict__ X1p,
                                                const float* __restrict__ Xp,
                                                const float* __restrict__ Wm,
                                                const float* __restrict__ Bm,
                                                const float* __restrict__ Wr,
                                                const float* __restrict__ b,
                                                float* __restrict__ OUT, int N)
{
    __shared__ float sw[768];
    int tid = threadIdx.x;
    if (tid < 256) { sw[tid] = Wm[tid]; sw[256 + tid] = Bm[tid]; sw[512 + tid] = Wr[tid]; }
    __syncthreads();

    int row = blockIdx.x * blockDim.x + tid;
    if (row >= N) return;

    float acc[4] = {0.f, 0.f, 0.f, 0.f};
    const float4* xe = reinterpret_cast<const float4*>(XEp + (size_t)row * 64);
    const float4* x1 = reinterpret_cast<const float4*>(X1p + (size_t)row * 64);
    const float4* xp = reinterpret_cast<const float4*>(Xp  + (size_t)row * 64);

    #pragma unroll 4
    for (int k4 = 0; k4 < 16; k4++) {
        float4 ve = __ldg(xe + k4);
        float4 v1 = __ldg(x1 + k4);
        float4 vx = __ldg(xp + k4);
        float es[4] = {ve.x, ve.y, ve.z, ve.w};
        float os[4] = {v1.x, v1.y, v1.z, v1.w};
        float xs[4] = {vx.x, vx.y, vx.z, vx.w};
        #pragma unroll
        for (int j = 0; j < 4; j++) {
            int k = k4 * 4 + j;
            #pragma unroll
            for (int c = 0; c < 4; c++) {
                acc[c] = fmaf(es[j], sw[k * 4 + c], acc[c]);
                acc[c] = fmaf(os[j], sw[256 + k * 4 + c], acc[c]);
                acc[c] = fmaf(xs[j], sw[512 + k * 4 + c], acc[c]);
            }
        }
    }
    #pragma unroll
    for (int c = 0; c < 4; c++) acc[c] += __ldg(b + c);

    float m = fmaxf(fmaxf(acc[0], acc[1]), fmaxf(acc[2], acc[3]));
    float s = __expf(acc[0] - m) + __expf(acc[1] - m) +
              __expf(acc[2] - m) + __expf(acc[3] - m);
    float lse = m + __logf(s);

    float4 o;
    o.x = acc[0] - lse; o.y = acc[1] - lse; o.z = acc[2] - lse; o.w = acc[3] - lse;
    *reinterpret_cast<float4*>(OUT + (size_t)row * 4) = o;
}

// =================================================================
extern "C" void kernel_launch(void* const* d_in, const int* in_sizes, int n_in,
                              void* d_out, int out_size)
{
    const float* x   = (const float*)d_in[0];
    const int*   ei  = (const int*)  d_in[1];
    const float* ea  = (const float*)d_in[2];
    const float* We1 = (const float*)d_in[3];
    const float* be1 = (const float*)d_in[4];
    const float* Wr1 = (const float*)d_in[5];
    const float* b1  = (const float*)d_in[6];
    const float* We2 = (const float*)d_in[7];
    const float* be2 = (const float*)d_in[8];
    const float* Wr2 = (const float*)d_in[9];
    const float* b2  = (const float*)d_in[10];
    const float* We3 = (const float*)d_in[11];
    const float* be3 = (const float*)d_in[12];
    const float* Wr3 = (const float*)d_in[13];
    const float* b3  = (const float*)d_in[14];

    const int N = in_sizes[0] / DIN;
    const int E = in_sizes[2];

    float *XE, *X1, *HA, *HB;
    int *counts, *off, *cursor;
    int2 *meta;
    cudaGetSymbolAddress((void**)&XE, g_XE);
    cudaGetSymbolAddress((void**)&X1, g_X1);
    cudaGetSymbolAddress((void**)&HA, g_HA);
    cudaGetSymbolAddress((void**)&HB, g_HB);
    cudaGetSymbolAddress((void**)&counts, g_counts);
    cudaGetSymbolAddress((void**)&off, g_off);
    cudaGetSymbolAddress((void**)&cursor, g_cursor);
    cudaGetSymbolAddress((void**)&meta, g_meta);
    float* OUT = (float*)d_out;

    cudaFuncSetAttribute(gemm192<false>, cudaFuncAttributeMaxDynamicSharedMemorySize, G_SMEM_BYTES);
    cudaFuncSetAttribute(gemm192<true>,  cudaFuncAttributeMaxDynamicSharedMemorySize, G_SMEM_BYTES);

    const int edgeGrid = (E + 255) / 256;
    const int rowGrid  = (N + 255) / 256;
    const int aggGrid  = (N * 32 + 255) / 256;
    const int gemmGrid = (N + 63) / 64;

    // ---- CSR build (reused by all 3 layers) ----
    cudaMemsetAsync(counts, 0, (size_t)N * sizeof(int));
    hist_kernel<<<edgeGrid, 256>>>(ei, counts, E);
    scan_kernel<<<1, 1024>>>(counts, off, cursor, N);
    scatter_kernel<<<edgeGrid, 256>>>(ei, ea, cursor, meta, E);

    // ---- layer 1 ----
    aggx_kernel<<<aggGrid, 256>>>(off, meta, x, XE, X1, N);
    gemm192<true><<<gemmGrid, 256, G_SMEM_BYTES>>>(XE, X1, x, We1, be1, Wr1, b1, HA, N);

    // ---- layer 2 ----
    aggx_kernel<<<aggGrid, 256>>>(off, meta, HA, XE, X1, N);
    gemm192<true><<<gemmGrid, 256, G_SMEM_BYTES>>>(XE, X1, HA, We2, be2, Wr2, b2, HB, N);

    // ---- layer 3 ----
    aggx_kernel<<<aggGrid, 256>>>(off, meta, HB, XE, X1, N);
    gemm3_ls<<<rowGrid, 256>>>(XE, X1, HB, We3, be3, Wr3, b3, OUT, N);
}

// round 6
// speedup vs baseline: 1.0493x; 1.0493x over previous
#include <cuda_runtime.h>
#include <cstdint>

#define MAXN 100000
#define MAXE 1600000
#define DIN  64

// ---------------- scratch (no cudaMalloc allowed) ----------------
__device__ float g_XE[(size_t)MAXN * 64];   // sum of e * X[src] per dst
__device__ float g_X1[(size_t)MAXN * 64];   // sum of X[src] per dst
__device__ float g_HA[(size_t)MAXN * 64];   // relu(layer1 out)
__device__ float g_HB[(size_t)MAXN * 64];   // relu(layer2 out)
__device__ int   g_counts[MAXN];
__device__ int   g_off[MAXN + 1];
__device__ int   g_cursor[MAXN];
__device__ int2  g_meta[MAXE];              // {src, bits(e)} grouped by dst

// =================================================================
// CSR build
// =================================================================
__global__ void zero_kernel(int* __restrict__ counts, int N)
{
    int i = blockIdx.x * blockDim.x + threadIdx.x;
    if (i < N) counts[i] = 0;
}

__global__ void hist_kernel(const int* __restrict__ ei, int* __restrict__ counts, int E)
{
    int e = blockIdx.x * blockDim.x + threadIdx.x;
    if (e < E) atomicAdd(&counts[__ldg(ei + E + e)], 1);
}

__global__ __launch_bounds__(1024) void scan_kernel(const int* __restrict__ counts,
                                                    int* __restrict__ off,
                                                    int* __restrict__ cursor, int N)
{
    __shared__ int ssum[1024];
    int tid = threadIdx.x;
    int chunk = (N + 1023) / 1024;
    int lo = tid * chunk;
    int hi = min(lo + chunk, N);
    int s = 0;
    for (int i = lo; i < hi; i++) s += counts[i];
    ssum[tid] = s;
    __syncthreads();
    for (int d = 1; d < 1024; d <<= 1) {
        int v = (tid >= d) ? ssum[tid - d] : 0;
        __syncthreads();
        ssum[tid] += v;
        __syncthreads();
    }
    int base = (tid == 0) ? 0 : ssum[tid - 1];
    for (int i = lo; i < hi; i++) {
        off[i] = base; cursor[i] = base;
        base += counts[i];
    }
    if (tid == 0) off[N] = ssum[1023];
}

__global__ void scatter_kernel(const int* __restrict__ ei, const float* __restrict__ ea,
                               int* __restrict__ cursor, int2* __restrict__ meta, int E)
{
    int e = blockIdx.x * blockDim.x + threadIdx.x;
    if (e >= E) return;
    int s = __ldg(ei + e);
    int d = __ldg(ei + E + e);
    int pos = atomicAdd(&cursor[d], 1);
    meta[pos] = make_int2(s, __float_as_int(__ldg(ea + e)));
}

// =================================================================
// Feature-space aggregation (measured 42us — unchanged):
// one warp per node, lane owns 2 channels, unroll-2
// =================================================================
__global__ __launch_bounds__(256) void aggx_kernel(const int* __restrict__ off,
                                                   const int2* __restrict__ meta,
                                                   const float* __restrict__ X,
                                                   float* __restrict__ XE,
                                                   float* __restrict__ X1, int N)
{
    int w = (blockIdx.x * blockDim.x + threadIdx.x) >> 5;
    int lane = threadIdx.x & 31;
    if (w >= N) return;

    int beg = __ldg(off + w);
    int end = __ldg(off + w + 1);

    float2 aE = make_float2(0.f, 0.f);
    float2 a1 = make_float2(0.f, 0.f);

    int k = beg;
    for (; k + 2 <= end; k += 2) {
        int2 m0 = __ldg(meta + k);
        int2 m1 = __ldg(meta + k + 1);
        float2 v0 = *reinterpret_cast<const float2*>(X + (size_t)m0.x * 64 + lane * 2);
        float2 v1 = *reinterpret_cast<const float2*>(X + (size_t)m1.x * 64 + lane * 2);
        float e0 = __int_as_float(m0.y);
        float e1 = __int_as_float(m1.y);
        aE.x = fmaf(e0, v0.x, aE.x); aE.y = fmaf(e0, v0.y, aE.y);
        aE.x = fmaf(e1, v1.x, aE.x); aE.y = fmaf(e1, v1.y, aE.y);
        a1.x += v0.x + v1.x;         a1.y += v0.y + v1.y;
    }
    if (k < end) {
        int2 m0 = __ldg(meta + k);
        float2 v0 = *reinterpret_cast<const float2*>(X + (size_t)m0.x * 64 + lane * 2);
        float e0 = __int_as_float(m0.y);
        aE.x = fmaf(e0, v0.x, aE.x); aE.y = fmaf(e0, v0.y, aE.y);
        a1.x += v0.x;                a1.y += v0.y;
    }

    *reinterpret_cast<float2*>(XE + (size_t)w * 64 + lane * 2) = aE;
    *reinterpret_cast<float2*>(X1 + (size_t)w * 64 + lane * 2) = a1;
}

// =================================================================
// K=192 fused GEMM on R2's proven skeleton:
// H = relu?(XE@Wm + X1@Bm + X@Wr + b)
// 256 threads, 32-row tile, 8 rows x 1 col per thread, 24 FMA/k.
// Wm/Bm staged in smem; Wr/bias via __ldg (L1) to keep smem at 60KB
// => 3 CTAs/SM, 24 warps (same occupancy as the measured-68us R2 gemm).
// =================================================================
#define TPAD 36
#define TILE_FLOATS (32 * 0 + 64 * TPAD)        /* 2304 */
#define G_SMEM_FLOATS (3 * TILE_FLOATS + 2 * 4096)
#define G_SMEM_BYTES  (G_SMEM_FLOATS * 4)       /* 60416 B */

template<bool RELU>
__global__ __launch_bounds__(256) void gemm192(const float* __restrict__ XEp,
                                               const float* __restrict__ X1p,
                                               const float* __restrict__ Xp,
                                               const float* __restrict__ Wm,
                                               const float* __restrict__ Bm,
                                               const float* __restrict__ Wr,
                                               const float* __restrict__ bias,
                                               float* __restrict__ H, int N)
{
    extern __shared__ float sm[];
    float* sT0 = sm;                        // XE tile [k*TPAD + r]
    float* sT1 = sm + TILE_FLOATS;          // X1 tile
    float* sT2 = sm + 2 * TILE_FLOATS;      // X  tile
    float* sWm = sm + 3 * TILE_FLOATS;
    float* sBm = sWm + 4096;

    const int tid = threadIdx.x;
    const int tx = tid & 63;                // output col
    const int ty = tid >> 6;                // 0..3, rows ty*8 .. +7
    const int row0 = blockIdx.x * 32;

    #pragma unroll
    for (int i = tid; i < 4096; i += 256) { sWm[i] = Wm[i]; sBm[i] = Bm[i]; }

    // stage 3 input tiles transposed (coalesced global reads)
    #pragma unroll
    for (int i = tid; i < 2048; i += 256) {
        int r = i >> 6;
        int k = i & 63;
        int row = row0 + r;
        bool ok = row < N;
        sT0[k * TPAD + r] = ok ? XEp[(size_t)row * 64 + k] : 0.f;
        sT1[k * TPAD + r] = ok ? X1p[(size_t)row * 64 + k] : 0.f;
        sT2[k * TPAD + r] = ok ? Xp [(size_t)row * 64 + k] : 0.f;
    }
    __syncthreads();

    float acc[8];
    #pragma unroll
    for (int r = 0; r < 8; r++) acc[r] = 0.f;

    #pragma unroll 4
    for (int k = 0; k < 64; k++) {
        float wm = sWm[k * 64 + tx];
        float wb = sBm[k * 64 + tx];
        float wr = __ldg(Wr + k * 64 + tx);

        const int xoff = k * TPAD + ty * 8;
        float4 a0 = *reinterpret_cast<const float4*>(&sT0[xoff]);
        float4 a1 = *reinterpret_cast<const float4*>(&sT0[xoff + 4]);
        float4 b0 = *reinterpret_cast<const float4*>(&sT1[xoff]);
        float4 b1 = *reinterpret_cast<const float4*>(&sT1[xoff + 4]);
        float4 c0 = *reinterpret_cast<const float4*>(&sT2[xoff]);
        float4 c1 = *reinterpret_cast<const float4*>(&sT2[xoff + 4]);

        float as[8] = {a0.x, a0.y, a0.z, a0.w, a1.x, a1.y, a1.z, a1.w};
        float bs[8] = {b0.x, b0.y, b0.z, b0.w, b1.x, b1.y, b1.z, b1.w};
        float cs[8] = {c0.x, c0.y, c0.z, c0.w, c1.x, c1.y, c1.z, c1.w};

        #pragma unroll
        for (int r = 0; r < 8; r++) {
            acc[r] = fmaf(as[r], wm, acc[r]);
            acc[r] = fmaf(bs[r], wb, acc[r]);
            acc[r] = fmaf(cs[r], wr, acc[r]);
        }
    }

    float b = __ldg(bias + tx);
    #pragma unroll
    for (int r = 0; r < 8; r++) {
        int row = row0 + ty * 8 + r;
        if (row < N) {
            float v = acc[r] + b;
            if (RELU) v = fmaxf(v, 0.f);
            H[(size_t)row * 64 + tx] = v;
        }
    }
}

// =================================================================
// Layer 3 + log_softmax fused
// =================================================================
__global__ __launch_bounds__(256) void gemm3_ls(const float* __restrict__ XEp,
                                                const float* __restrict__ X1p,
                                                const float* __restrict__ Xp,
                                                const float* __restrict__ Wm,
                                                const float* __restrict__ Bm,
                                                const float* __restrict__ Wr,
                                                const float* __restrict__ b,
                                                float* __restrict__ OUT, int N)
{
    __shared__ float sw[768];
    int tid = threadIdx.x;
    if (tid < 256) { sw[tid] = Wm[tid]; sw[256 + tid] = Bm[tid]; sw[512 + tid] = Wr[tid]; }
    __syncthreads();

    int row = blockIdx.x * blockDim.x + tid;
    if (row >= N) return;

    float acc[4] = {0.f, 0.f, 0.f, 0.f};
    const float4* xe = reinterpret_cast<const float4*>(XEp + (size_t)row * 64);
    const float4* x1 = reinterpret_cast<const float4*>(X1p + (size_t)row * 64);
    const float4* xp = reinterpret_cast<const float4*>(Xp  + (size_t)row * 64);

    #pragma unroll 4
    for (int k4 = 0; k4 < 16; k4++) {
        float4 ve = __ldg(xe + k4);
        float4 v1 = __ldg(x1 + k4);
        float4 vx = __ldg(xp + k4);
        float es[4] = {ve.x, ve.y, ve.z, ve.w};
        float os[4] = {v1.x, v1.y, v1.z, v1.w};
        float xs[4] = {vx.x, vx.y, vx.z, vx.w};
        #pragma unroll
        for (int j = 0; j < 4; j++) {
            int k = k4 * 4 + j;
            #pragma unroll
            for (int c = 0; c < 4; c++) {
                acc[c] = fmaf(es[j], sw[k * 4 + c], acc[c]);
                acc[c] = fmaf(os[j], sw[256 + k * 4 + c], acc[c]);
                acc[c] = fmaf(xs[j], sw[512 + k * 4 + c], acc[c]);
            }
        }
    }
    #pragma unroll
    for (int c = 0; c < 4; c++) acc[c] += __ldg(b + c);

    float m = fmaxf(fmaxf(acc[0], acc[1]), fmaxf(acc[2], acc[3]));
    float s = __expf(acc[0] - m) + __expf(acc[1] - m) +
              __expf(acc[2] - m) + __expf(acc[3] - m);
    float lse = m + __logf(s);

    float4 o;
    o.x = acc[0] - lse; o.y = acc[1] - lse; o.z = acc[2] - lse; o.w = acc[3] - lse;
    *reinterpret_cast<float4*>(OUT + (size_t)row * 4) = o;
}

// =================================================================
extern "C" void kernel_launch(void* const* d_in, const int* in_sizes, int n_in,
                              void* d_out, int out_size)
{
    const float* x   = (const float*)d_in[0];
    const int*   ei  = (const int*)  d_in[1];
    const float* ea  = (const float*)d_in[2];
    const float* We1 = (const float*)d_in[3];
    const float* be1 = (const float*)d_in[4];
    const float* Wr1 = (const float*)d_in[5];
    const float* b1  = (const float*)d_in[6];
    const float* We2 = (const float*)d_in[7];
    const float* be2 = (const float*)d_in[8];
    const float* Wr2 = (const float*)d_in[9];
    const float* b2  = (const float*)d_in[10];
    const float* We3 = (const float*)d_in[11];
    const float* be3 = (const float*)d_in[12];
    const float* Wr3 = (const float*)d_in[13];
    const float* b3  = (const float*)d_in[14];

    const int N = in_sizes[0] / DIN;
    const int E = in_sizes[2];

    float *XE, *X1, *HA, *HB;
    int *counts, *off, *cursor;
    int2 *meta;
    cudaGetSymbolAddress((void**)&XE, g_XE);
    cudaGetSymbolAddress((void**)&X1, g_X1);
    cudaGetSymbolAddress((void**)&HA, g_HA);
    cudaGetSymbolAddress((void**)&HB, g_HB);
    cudaGetSymbolAddress((void**)&counts, g_counts);
    cudaGetSymbolAddress((void**)&off, g_off);
    cudaGetSymbolAddress((void**)&cursor, g_cursor);
    cudaGetSymbolAddress((void**)&meta, g_meta);
    float* OUT = (float*)d_out;

    cudaFuncSetAttribute(gemm192<false>, cudaFuncAttributeMaxDynamicSharedMemorySize, G_SMEM_BYTES);
    cudaFuncSetAttribute(gemm192<true>,  cudaFuncAttributeMaxDynamicSharedMemorySize, G_SMEM_BYTES);

    const int edgeGrid = (E + 255) / 256;
    const int rowGrid  = (N + 255) / 256;
    const int aggGrid  = (N * 32 + 255) / 256;
    const int gemmGrid = (N + 31) / 32;

    // ---- CSR build (launch #0..#3; keeps ncu capture (-s 5) on gemm192) ----
    zero_kernel<<<rowGrid, 256>>>(counts, N);
    hist_kernel<<<edgeGrid, 256>>>(ei, counts, E);
    scan_kernel<<<1, 1024>>>(counts, off, cursor, N);
    scatter_kernel<<<edgeGrid, 256>>>(ei, ea, cursor, meta, E);

    // ---- layer 1 (aggx = launch #4, gemm192 = launch #5 -> ncu captures it)
    aggx_kernel<<<aggGrid, 256>>>(off, meta, x, XE, X1, N);
    gemm192<true><<<gemmGrid, 256, G_SMEM_BYTES>>>(XE, X1, x, We1, be1, Wr1, b1, HA, N);

    // ---- layer 2 ----
    aggx_kernel<<<aggGrid, 256>>>(off, meta, HA, XE, X1, N);
    gemm192<true><<<gemmGrid, 256, G_SMEM_BYTES>>>(XE, X1, HA, We2, be2, Wr2, b2, HB, N);

    // ---- layer 3 ----
    aggx_kernel<<<aggGrid, 256>>>(off, meta, HB, XE, X1, N);
    gemm3_ls<<<rowGrid, 256>>>(XE, X1, HB, We3, be3, Wr3, b3, OUT, N);
}

// round 7
// speedup vs baseline: 1.5049x; 1.4341x over previous
#include <cuda_runtime.h>
#include <cstdint>

#define MAXN 100000
#define MAXE 1600000
#define DIN  64

// ---------------- scratch (no cudaMalloc allowed) ----------------
__device__ float g_XE[(size_t)MAXN * 64];   // sum of e * X[src] per dst
__device__ float g_X1[(size_t)MAXN * 64];   // sum of X[src] per dst
__device__ float g_HA[(size_t)MAXN * 64];   // relu(layer1 out)
__device__ float g_HB[(size_t)MAXN * 64];   // relu(layer2 out)
__device__ int   g_counts[MAXN];
__device__ int   g_off[MAXN + 1];
__device__ int   g_cursor[MAXN];
__device__ int   g_bsum[64];
__device__ int   g_boff[64];
__device__ int2  g_meta[MAXE];              // {src, bits(e)} grouped by dst

// =================================================================
// CSR build
// =================================================================
__global__ void zero_kernel(int* __restrict__ counts, int N)
{
    int i = blockIdx.x * blockDim.x + threadIdx.x;
    if (i < N) counts[i] = 0;
}

__global__ void hist_kernel(const int* __restrict__ ei, int* __restrict__ counts, int E)
{
    int e = blockIdx.x * blockDim.x + threadIdx.x;
    if (e < E) atomicAdd(&counts[__ldg(ei + E + e)], 1);
}

// Phase A: per-block (2048 elems) reduction, coalesced int4 loads
__global__ __launch_bounds__(256) void scanA_kernel(const int* __restrict__ counts,
                                                    int* __restrict__ bsum, int N)
{
    __shared__ int red[256];
    int tid = threadIdx.x;
    int base = blockIdx.x * 2048 + tid * 8;
    int s = 0;
    if (base < N) {
        int4 a = *reinterpret_cast<const int4*>(counts + base);
        int4 b = *reinterpret_cast<const int4*>(counts + base + 4);
        s = a.x + a.y + a.z + a.w + b.x + b.y + b.z + b.w;
    }
    red[tid] = s;
    __syncthreads();
    #pragma unroll
    for (int d = 128; d > 0; d >>= 1) {
        if (tid < d) red[tid] += red[tid + d];
        __syncthreads();
    }
    if (tid == 0) bsum[blockIdx.x] = red[0];
}

// Phase B: scan block sums (B <= 64), one tiny block
__global__ __launch_bounds__(64) void scanB_kernel(const int* __restrict__ bsum,
                                                   int* __restrict__ boff,
                                                   int* __restrict__ off, int B, int N)
{
    __shared__ int sh[64];
    int tid = threadIdx.x;
    int v = (tid < B) ? bsum[tid] : 0;
    sh[tid] = v;
    __syncthreads();
    #pragma unroll
    for (int d = 1; d < 64; d <<= 1) {
        int t = (tid >= d) ? sh[tid - d] : 0;
        __syncthreads();
        sh[tid] += t;
        __syncthreads();
    }
    boff[tid] = sh[tid] - v;         // exclusive
    if (tid == 63) off[N] = sh[63];  // total edge count
}

// Phase C: per-block exclusive scan, writes off + cursor
__global__ __launch_bounds__(256) void scanC_kernel(const int* __restrict__ counts,
                                                    const int* __restrict__ boff,
                                                    int* __restrict__ off,
                                                    int* __restrict__ cursor, int N)
{
    __shared__ int wsum[8], woff[8];
    int tid = threadIdx.x;
    int lane = tid & 31;
    int warp = tid >> 5;
    int base = blockIdx.x * 2048 + tid * 8;

    int4 a = make_int4(0, 0, 0, 0), b = make_int4(0, 0, 0, 0);
    if (base < N) {
        a = *reinterpret_cast<const int4*>(counts + base);
        b = *reinterpret_cast<const int4*>(counts + base + 4);
    }
    int s = a.x + a.y + a.z + a.w + b.x + b.y + b.z + b.w;

    int incl = s;
    #pragma unroll
    for (int d = 1; d < 32; d <<= 1) {
        int t = __shfl_up_sync(0xFFFFFFFFu, incl, d);
        if (lane >= d) incl += t;
    }
    if (lane == 31) wsum[warp] = incl;
    __syncthreads();
    if (tid == 0) {
        int run = 0;
        #pragma unroll
        for (int j = 0; j < 8; j++) { int t = wsum[j]; woff[j] = run; run += t; }
    }
    __syncthreads();

    int ex = __ldg(boff + blockIdx.x) + woff[warp] + (incl - s);
    if (base < N) {
        int o0 = ex;
        int o1 = o0 + a.x, o2 = o1 + a.y, o3 = o2 + a.z, o4 = o3 + a.w;
        int o5 = o4 + b.x, o6 = o5 + b.y, o7 = o6 + b.z;
        int4 oa = make_int4(o0, o1, o2, o3);
        int4 ob = make_int4(o4, o5, o6, o7);
        *reinterpret_cast<int4*>(off + base)        = oa;
        *reinterpret_cast<int4*>(off + base + 4)    = ob;
        *reinterpret_cast<int4*>(cursor + base)     = oa;
        *reinterpret_cast<int4*>(cursor + base + 4) = ob;
    }
}

__global__ void scatter_kernel(const int* __restrict__ ei, const float* __restrict__ ea,
                               int* __restrict__ cursor, int2* __restrict__ meta, int E)
{
    int e = blockIdx.x * blockDim.x + threadIdx.x;
    if (e >= E) return;
    int s = __ldg(ei + e);
    int d = __ldg(ei + E + e);
    int pos = atomicAdd(&cursor[d], 1);
    meta[pos] = make_int2(s, __float_as_int(__ldg(ea + e)));
}

// =================================================================
// Feature-space aggregation (measured 42us — unchanged):
// one warp per node, lane owns 2 channels, unroll-2
// =================================================================
__global__ __launch_bounds__(256) void aggx_kernel(const int* __restrict__ off,
                                                   const int2* __restrict__ meta,
                                                   const float* __restrict__ X,
                                                   float* __restrict__ XE,
                                                   float* __restrict__ X1, int N)
{
    int w = (blockIdx.x * blockDim.x + threadIdx.x) >> 5;
    int lane = threadIdx.x & 31;
    if (w >= N) return;

    int beg = __ldg(off + w);
    int end = __ldg(off + w + 1);

    float2 aE = make_float2(0.f, 0.f);
    float2 a1 = make_float2(0.f, 0.f);

    int k = beg;
    for (; k + 2 <= end; k += 2) {
        int2 m0 = __ldg(meta + k);
        int2 m1 = __ldg(meta + k + 1);
        float2 v0 = *reinterpret_cast<const float2*>(X + (size_t)m0.x * 64 + lane * 2);
        float2 v1 = *reinterpret_cast<const float2*>(X + (size_t)m1.x * 64 + lane * 2);
        float e0 = __int_as_float(m0.y);
        float e1 = __int_as_float(m1.y);
        aE.x = fmaf(e0, v0.x, aE.x); aE.y = fmaf(e0, v0.y, aE.y);
        aE.x = fmaf(e1, v1.x, aE.x); aE.y = fmaf(e1, v1.y, aE.y);
        a1.x += v0.x + v1.x;         a1.y += v0.y + v1.y;
    }
    if (k < end) {
        int2 m0 = __ldg(meta + k);
        float2 v0 = *reinterpret_cast<const float2*>(X + (size_t)m0.x * 64 + lane * 2);
        float e0 = __int_as_float(m0.y);
        aE.x = fmaf(e0, v0.x, aE.x); aE.y = fmaf(e0, v0.y, aE.y);
        a1.x += v0.x;                a1.y += v0.y;
    }

    *reinterpret_cast<float2*>(XE + (size_t)w * 64 + lane * 2) = aE;
    *reinterpret_cast<float2*>(X1 + (size_t)w * 64 + lane * 2) = a1;
}

// =================================================================
// K=192 fused GEMM: H = relu?(XE@Wm + X1@Bm + X@Wr + b)
// 128 threads, 32-row tile, 2 cols x 8 rows per thread.
// Per k per thread: 6 LDS.128(bcast) + 2 LDS.64 + 1 LDG.64 vs 48 FMA
// => FMA-bound. smem 60.4KB => 3 CTAs/SM.
// =================================================================
#define TPAD 36
#define TILE_FLOATS (64 * TPAD)                 /* 2304 */
#define G_SMEM_FLOATS (3 * TILE_FLOATS + 2 * 4096)
#define G_SMEM_BYTES  (G_SMEM_FLOATS * 4)       /* 60416 B */

template<bool RELU>
__global__ __launch_bounds__(128) void gemm192(const float* __restrict__ XEp,
                                               const float* __restrict__ X1p,
                                               const float* __restrict__ Xp,
                                               const float* __restrict__ Wm,
                                               const float* __restrict__ Bm,
                                               const float* __restrict__ Wr,
                                               const float* __restrict__ bias,
                                               float* __restrict__ H, int N)
{
    extern __shared__ float sm[];
    float* sT0 = sm;                        // XE tile [k*TPAD + r]
    float* sT1 = sm + TILE_FLOATS;          // X1 tile
    float* sT2 = sm + 2 * TILE_FLOATS;      // X  tile
    float* sWm = sm + 3 * TILE_FLOATS;
    float* sBm = sWm + 4096;

    const int tid = threadIdx.x;
    const int txc = (tid & 31) * 2;         // output col pair
    const int ty  = tid >> 5;               // 0..3, rows ty*8 .. +7
    const int row0 = blockIdx.x * 32;

    #pragma unroll
    for (int i = tid; i < 4096; i += 128) { sWm[i] = Wm[i]; sBm[i] = Bm[i]; }

    // stage 3 input tiles transposed (coalesced global reads)
    #pragma unroll
    for (int i = tid; i < 2048; i += 128) {
        int r = i >> 6;
        int k = i & 63;
        int row = row0 + r;
        bool ok = row < N;
        sT0[k * TPAD + r] = ok ? XEp[(size_t)row * 64 + k] : 0.f;
        sT1[k * TPAD + r] = ok ? X1p[(size_t)row * 64 + k] : 0.f;
        sT2[k * TPAD + r] = ok ? Xp [(size_t)row * 64 + k] : 0.f;
    }
    __syncthreads();

    float2 acc[8];
    #pragma unroll
    for (int r = 0; r < 8; r++) acc[r] = make_float2(0.f, 0.f);

    #pragma unroll 4
    for (int k = 0; k < 64; k++) {
        float2 wm = *reinterpret_cast<const float2*>(&sWm[k * 64 + txc]);
        float2 wb = *reinterpret_cast<const float2*>(&sBm[k * 64 + txc]);
        float2 wr = __ldg(reinterpret_cast<const float2*>(Wr + k * 64 + txc));

        const int xoff = k * TPAD + ty * 8;
        float4 a0 = *reinterpret_cast<const float4*>(&sT0[xoff]);
        float4 a1 = *reinterpret_cast<const float4*>(&sT0[xoff + 4]);
        float4 b0 = *reinterpret_cast<const float4*>(&sT1[xoff]);
        float4 b1 = *reinterpret_cast<const float4*>(&sT1[xoff + 4]);
        float4 c0 = *reinterpret_cast<const float4*>(&sT2[xoff]);
        float4 c1 = *reinterpret_cast<const float4*>(&sT2[xoff + 4]);

        float as[8] = {a0.x, a0.y, a0.z, a0.w, a1.x, a1.y, a1.z, a1.w};
        float bs[8] = {b0.x, b0.y, b0.z, b0.w, b1.x, b1.y, b1.z, b1.w};
        float cs[8] = {c0.x, c0.y, c0.z, c0.w, c1.x, c1.y, c1.z, c1.w};

        #pragma unroll
        for (int r = 0; r < 8; r++) {
            acc[r].x = fmaf(as[r], wm.x, acc[r].x);
            acc[r].y = fmaf(as[r], wm.y, acc[r].y);
            acc[r].x = fmaf(bs[r], wb.x, acc[r].x);
            acc[r].y = fmaf(bs[r], wb.y, acc[r].y);
            acc[r].x = fmaf(cs[r], wr.x, acc[r].x);
            acc[r].y = fmaf(cs[r], wr.y, acc[r].y);
        }
    }

    float2 b2 = __ldg(reinterpret_cast<const float2*>(bias + txc));
    #pragma unroll
    for (int r = 0; r < 8; r++) {
        int row = row0 + ty * 8 + r;
        if (row < N) {
            float2 v;
            v.x = acc[r].x + b2.x;
            v.y = acc[r].y + b2.y;
            if (RELU) { v.x = fmaxf(v.x, 0.f); v.y = fmaxf(v.y, 0.f); }
            *reinterpret_cast<float2*>(H + (size_t)row * 64 + txc) = v;
        }
    }
}

// =================================================================
// Layer 3 + log_softmax fused
// =================================================================
__global__ __launch_bounds__(256) void gemm3_ls(const float* __restrict__ XEp,
                                                const float* __restrict__ X1p,
                                                const float* __restrict__ Xp,
                                                const float* __restrict__ Wm,
                                                const float* __restrict__ Bm,
                                                const float* __restrict__ Wr,
                                                const float* __restrict__ b,
                                                float* __restrict__ OUT, int N)
{
    __shared__ float sw[768];
    int tid = threadIdx.x;
    if (tid < 256) { sw[tid] = Wm[tid]; sw[256 + tid] = Bm[tid]; sw[512 + tid] = Wr[tid]; }
    __syncthreads();

    int row = blockIdx.x * blockDim.x + tid;
    if (row >= N) return;

    float acc[4] = {0.f, 0.f, 0.f, 0.f};
    const float4* xe = reinterpret_cast<const float4*>(XEp + (size_t)row * 64);
    const float4* x1 = reinterpret_cast<const float4*>(X1p + (size_t)row * 64);
    const float4* xp = reinterpret_cast<const float4*>(Xp  + (size_t)row * 64);

    #pragma unroll 4
    for (int k4 = 0; k4 < 16; k4++) {
        float4 ve = __ldg(xe + k4);
        float4 v1 = __ldg(x1 + k4);
        float4 vx = __ldg(xp + k4);
        float es[4] = {ve.x, ve.y, ve.z, ve.w};
        float os[4] = {v1.x, v1.y, v1.z, v1.w};
        float xs[4] = {vx.x, vx.y, vx.z, vx.w};
        #pragma unroll
        for (int j = 0; j < 4; j++) {
            int k = k4 * 4 + j;
            #pragma unroll
            for (int c = 0; c < 4; c++) {
                acc[c] = fmaf(es[j], sw[k * 4 + c], acc[c]);
                acc[c] = fmaf(os[j], sw[256 + k * 4 + c], acc[c]);
                acc[c] = fmaf(xs[j], sw[512 + k * 4 + c], acc[c]);
            }
        }
    }
    #pragma unroll
    for (int c = 0; c < 4; c++) acc[c] += __ldg(b + c);

    float m = fmaxf(fmaxf(acc[0], acc[1]), fmaxf(acc[2], acc[3]));
    float s = __expf(acc[0] - m) + __expf(acc[1] - m) +
              __expf(acc[2] - m) + __expf(acc[3] - m);
    float lse = m + __logf(s);

    float4 o;
    o.x = acc[0] - lse; o.y = acc[1] - lse; o.z = acc[2] - lse; o.w = acc[3] - lse;
    *reinterpret_cast<float4*>(OUT + (size_t)row * 4) = o;
}

// =================================================================
extern "C" void kernel_launch(void* const* d_in, const int* in_sizes, int n_in,
                              void* d_out, int out_size)
{
    const float* x   = (const float*)d_in[0];
    const int*   ei  = (const int*)  d_in[1];
    const float* ea  = (const float*)d_in[2];
    const float* We1 = (const float*)d_in[3];
    const float* be1 = (const float*)d_in[4];
    const float* Wr1 = (const float*)d_in[5];
    const float* b1  = (const float*)d_in[6];
    const float* We2 = (const float*)d_in[7];
    const float* be2 = (const float*)d_in[8];
    const float* Wr2 = (const float*)d_in[9];
    const float* b2  = (const float*)d_in[10];
    const float* We3 = (const float*)d_in[11];
    const float* be3 = (const float*)d_in[12];
    const float* Wr3 = (const float*)d_in[13];
    const float* b3  = (const float*)d_in[14];

    const int N = in_sizes[0] / DIN;
    const int E = in_sizes[2];

    float *XE, *X1, *HA, *HB;
    int *counts, *off, *cursor, *bsum, *boff;
    int2 *meta;
    cudaGetSymbolAddress((void**)&XE, g_XE);
    cudaGetSymbolAddress((void**)&X1, g_X1);
    cudaGetSymbolAddress((void**)&HA, g_HA);
    cudaGetSymbolAddress((void**)&HB, g_HB);
    cudaGetSymbolAddress((void**)&counts, g_counts);
    cudaGetSymbolAddress((void**)&off, g_off);
    cudaGetSymbolAddress((void**)&cursor, g_cursor);
    cudaGetSymbolAddress((void**)&bsum, g_bsum);
    cudaGetSymbolAddress((void**)&boff, g_boff);
    cudaGetSymbolAddress((void**)&meta, g_meta);
    float* OUT = (float*)d_out;

    cudaFuncSetAttribute(gemm192<false>, cudaFuncAttributeMaxDynamicSharedMemorySize, G_SMEM_BYTES);
    cudaFuncSetAttribute(gemm192<true>,  cudaFuncAttributeMaxDynamicSharedMemorySize, G_SMEM_BYTES);

    const int edgeGrid = (E + 255) / 256;
    const int rowGrid  = (N + 255) / 256;
    const int aggGrid  = (N * 32 + 255) / 256;
    const int gemmGrid = (N + 31) / 32;
    const int scanGrid = (N + 2047) / 2048;     // 49 blocks

    // ---- CSR build (reused by all 3 layers) ----
    zero_kernel<<<rowGrid, 256>>>(counts, N);
    hist_kernel<<<edgeGrid, 256>>>(ei, counts, E);
    scanA_kernel<<<scanGrid, 256>>>(counts, bsum, N);
    scanB_kernel<<<1, 64>>>(bsum, boff, off, scanGrid, N);
    scanC_kernel<<<scanGrid, 256>>>(counts, boff, off, cursor, N);
    scatter_kernel<<<edgeGrid, 256>>>(ei, ea, cursor, meta, E);

    // ---- layer 1 ----
    aggx_kernel<<<aggGrid, 256>>>(off, meta, x, XE, X1, N);
    gemm192<true><<<gemmGrid, 128, G_SMEM_BYTES>>>(XE, X1, x, We1, be1, Wr1, b1, HA, N);

    // ---- layer 2 ----
    aggx_kernel<<<aggGrid, 256>>>(off, meta, HA, XE, X1, N);
    gemm192<true><<<gemmGrid, 128, G_SMEM_BYTES>>>(XE, X1, HA, We2, be2, Wr2, b2, HB, N);

    // ---- layer 3 ----
    aggx_kernel<<<aggGrid, 256>>>(off, meta, HB, XE, X1, N);
    gemm3_ls<<<rowGrid, 256>>>(XE, X1, HB, We3, be3, Wr3, b3, OUT, N);
}

// round 8
// speedup vs baseline: 1.7832x; 1.1850x over previous
#include <cuda_runtime.h>
#include <cstdint>

#define MAXN 100000
#define MAXE 1600000
#define DIN  64

// ---------------- scratch (no cudaMalloc allowed) ----------------
__device__ float g_XE[(size_t)MAXN * 64];   // sum of e * X[src] per dst
__device__ float g_X1[(size_t)MAXN * 64];   // sum of X[src] per dst
__device__ float g_HA[(size_t)MAXN * 64];   // relu(layer1 out)
__device__ float g_HB[(size_t)MAXN * 64];   // relu(layer2 out)
__device__ int   g_counts[MAXN];
__device__ int   g_off[MAXN + 1];
__device__ int   g_cursor[MAXN];
__device__ int   g_bsum[64];
__device__ int   g_boff[64];
__device__ int2  g_meta[MAXE];              // {src, bits(e)} grouped by dst

// =================================================================
// CSR build (unchanged from R7 winner)
// =================================================================
__global__ void zero_kernel(int* __restrict__ counts, int N)
{
    int i = blockIdx.x * blockDim.x + threadIdx.x;
    if (i < N) counts[i] = 0;
}

__global__ void hist_kernel(const int* __restrict__ ei, int* __restrict__ counts, int E)
{
    int e = blockIdx.x * blockDim.x + threadIdx.x;
    if (e < E) atomicAdd(&counts[__ldg(ei + E + e)], 1);
}

__global__ __launch_bounds__(256) void scanA_kernel(const int* __restrict__ counts,
                                                    int* __restrict__ bsum, int N)
{
    __shared__ int red[256];
    int tid = threadIdx.x;
    int base = blockIdx.x * 2048 + tid * 8;
    int s = 0;
    if (base < N) {
        int4 a = *reinterpret_cast<const int4*>(counts + base);
        int4 b = *reinterpret_cast<const int4*>(counts + base + 4);
        s = a.x + a.y + a.z + a.w + b.x + b.y + b.z + b.w;
    }
    red[tid] = s;
    __syncthreads();
    #pragma unroll
    for (int d = 128; d > 0; d >>= 1) {
        if (tid < d) red[tid] += red[tid + d];
        __syncthreads();
    }
    if (tid == 0) bsum[blockIdx.x] = red[0];
}

__global__ __launch_bounds__(64) void scanB_kernel(const int* __restrict__ bsum,
                                                   int* __restrict__ boff,
                                                   int* __restrict__ off, int B, int N)
{
    __shared__ int sh[64];
    int tid = threadIdx.x;
    int v = (tid < B) ? bsum[tid] : 0;
    sh[tid] = v;
    __syncthreads();
    #pragma unroll
    for (int d = 1; d < 64; d <<= 1) {
        int t = (tid >= d) ? sh[tid - d] : 0;
        __syncthreads();
        sh[tid] += t;
        __syncthreads();
    }
    boff[tid] = sh[tid] - v;
    if (tid == 63) off[N] = sh[63];
}

__global__ __launch_bounds__(256) void scanC_kernel(const int* __restrict__ counts,
                                                    const int* __restrict__ boff,
                                                    int* __restrict__ off,
                                                    int* __restrict__ cursor, int N)
{
    __shared__ int wsum[8], woff[8];
    int tid = threadIdx.x;
    int lane = tid & 31;
    int warp = tid >> 5;
    int base = blockIdx.x * 2048 + tid * 8;

    int4 a = make_int4(0, 0, 0, 0), b = make_int4(0, 0, 0, 0);
    if (base < N) {
        a = *reinterpret_cast<const int4*>(counts + base);
        b = *reinterpret_cast<const int4*>(counts + base + 4);
    }
    int s = a.x + a.y + a.z + a.w + b.x + b.y + b.z + b.w;

    int incl = s;
    #pragma unroll
    for (int d = 1; d < 32; d <<= 1) {
        int t = __shfl_up_sync(0xFFFFFFFFu, incl, d);
        if (lane >= d) incl += t;
    }
    if (lane == 31) wsum[warp] = incl;
    __syncthreads();
    if (tid == 0) {
        int run = 0;
        #pragma unroll
        for (int j = 0; j < 8; j++) { int t = wsum[j]; woff[j] = run; run += t; }
    }
    __syncthreads();

    int ex = __ldg(boff + blockIdx.x) + woff[warp] + (incl - s);
    if (base < N) {
        int o0 = ex;
        int o1 = o0 + a.x, o2 = o1 + a.y, o3 = o2 + a.z, o4 = o3 + a.w;
        int o5 = o4 + b.x, o6 = o5 + b.y, o7 = o6 + b.z;
        int4 oa = make_int4(o0, o1, o2, o3);
        int4 ob = make_int4(o4, o5, o6, o7);
        *reinterpret_cast<int4*>(off + base)        = oa;
        *reinterpret_cast<int4*>(off + base + 4)    = ob;
        *reinterpret_cast<int4*>(cursor + base)     = oa;
        *reinterpret_cast<int4*>(cursor + base + 4) = ob;
    }
}

__global__ void scatter_kernel(const int* __restrict__ ei, const float* __restrict__ ea,
                               int* __restrict__ cursor, int2* __restrict__ meta, int E)
{
    int e = blockIdx.x * blockDim.x + threadIdx.x;
    if (e >= E) return;
    int s = __ldg(ei + e);
    int d = __ldg(ei + E + e);
    int pos = atomicAdd(&cursor[d], 1);
    meta[pos] = make_int2(s, __float_as_int(__ldg(ea + e)));
}

// =================================================================
// Feature-space aggregation (measured 42us — unchanged)
// =================================================================
__global__ __launch_bounds__(256) void aggx_kernel(const int* __restrict__ off,
                                                   const int2* __restrict__ meta,
                                                   const float* __restrict__ X,
                                                   float* __restrict__ XE,
                                                   float* __restrict__ X1, int N)
{
    int w = (blockIdx.x * blockDim.x + threadIdx.x) >> 5;
    int lane = threadIdx.x & 31;
    if (w >= N) return;

    int beg = __ldg(off + w);
    int end = __ldg(off + w + 1);

    float2 aE = make_float2(0.f, 0.f);
    float2 a1 = make_float2(0.f, 0.f);

    int k = beg;
    for (; k + 2 <= end; k += 2) {
        int2 m0 = __ldg(meta + k);
        int2 m1 = __ldg(meta + k + 1);
        float2 v0 = *reinterpret_cast<const float2*>(X + (size_t)m0.x * 64 + lane * 2);
        float2 v1 = *reinterpret_cast<const float2*>(X + (size_t)m1.x * 64 + lane * 2);
        float e0 = __int_as_float(m0.y);
        float e1 = __int_as_float(m1.y);
        aE.x = fmaf(e0, v0.x, aE.x); aE.y = fmaf(e0, v0.y, aE.y);
        aE.x = fmaf(e1, v1.x, aE.x); aE.y = fmaf(e1, v1.y, aE.y);
        a1.x += v0.x + v1.x;         a1.y += v0.y + v1.y;
    }
    if (k < end) {
        int2 m0 = __ldg(meta + k);
        float2 v0 = *reinterpret_cast<const float2*>(X + (size_t)m0.x * 64 + lane * 2);
        float e0 = __int_as_float(m0.y);
        aE.x = fmaf(e0, v0.x, aE.x); aE.y = fmaf(e0, v0.y, aE.y);
        a1.x += v0.x;                a1.y += v0.y;
    }

    *reinterpret_cast<float2*>(XE + (size_t)w * 64 + lane * 2) = aE;
    *reinterpret_cast<float2*>(X1 + (size_t)w * 64 + lane * 2) = a1;
}

// =================================================================
// 3xTF32 tensor-core GEMM: H = relu?(XE@Wm + X1@Bm + X@Wr + b)
// CTA: 128 rows x 64 cols, 256 threads = 8 warps (warp tile 32x32).
// K=192 as 3 segments; hi/lo tf32 split done once at staging.
// mma.sync.aligned.m16n8k8.row.col.f32.tf32.tf32.f32
// =================================================================
#define APAD 68
#define SA_FLOATS (128 * APAD)     /* 8704  */
#define SW_FLOATS (64 * APAD)      /* 4352  */
#define TC_SMEM_FLOATS (2 * SA_FLOATS + 2 * SW_FLOATS)
#define TC_SMEM_BYTES  (TC_SMEM_FLOATS * 4)   /* 104448 B */

__device__ __forceinline__ void split_tf32(float v, uint32_t& hi, uint32_t& lo)
{
    asm("cvt.rna.tf32.f32 %0, %1;" : "=r"(hi) : "f"(v));
    float r = v - __uint_as_float(hi);
    asm("cvt.rna.tf32.f32 %0, %1;" : "=r"(lo) : "f"(r));
}

__device__ __forceinline__ void mma_tf32(float* c, const uint32_t* a, const uint32_t* b)
{
    asm("mma.sync.aligned.m16n8k8.row.col.f32.tf32.tf32.f32 "
        "{%0,%1,%2,%3}, {%4,%5,%6,%7}, {%8,%9}, {%0,%1,%2,%3};"
        : "+f"(c[0]), "+f"(c[1]), "+f"(c[2]), "+f"(c[3])
        : "r"(a[0]), "r"(a[1]), "r"(a[2]), "r"(a[3]), "r"(b[0]), "r"(b[1]));
}

template<bool RELU>
__global__ __launch_bounds__(256, 2) void gemm192_tc(const float* __restrict__ XEp,
                                                     const float* __restrict__ X1p,
                                                     const float* __restrict__ Xp,
                                                     const float* __restrict__ Wm,
                                                     const float* __restrict__ Bm,
                                                     const float* __restrict__ Wr,
                                                     const float* __restrict__ bias,
                                                     float* __restrict__ H, int N)
{
    extern __shared__ float sm[];
    float* sAhi = sm;                       // [row*APAD + k], 128x64
    float* sAlo = sAhi + SA_FLOATS;
    float* sWhi = sAlo + SA_FLOATS;         // transposed: [n*APAD + k], 64x64
    float* sWlo = sWhi + SW_FLOATS;

    const int tid  = threadIdx.x;
    const int lane = tid & 31;
    const int wid  = tid >> 5;
    const int grp  = lane >> 2;             // 0..7
    const int qid  = lane & 3;              // 0..3
    const int wm   = wid & 3;               // warp row 0..3 -> rows wm*32
    const int wn   = wid >> 2;              // warp col 0..1 -> cols wn*32
    const int row0 = blockIdx.x * 128;

    float c[2][4][4];                        // [mtile][ntile][frag]
    #pragma unroll
    for (int mt = 0; mt < 2; mt++)
        #pragma unroll
        for (int nt = 0; nt < 4; nt++)
            #pragma unroll
            for (int j = 0; j < 4; j++) c[mt][nt][j] = 0.f;

    #pragma unroll
    for (int seg = 0; seg < 3; seg++) {
        const float* A = (seg == 0) ? XEp : (seg == 1) ? X1p : Xp;
        const float* W = (seg == 0) ? Wm  : (seg == 1) ? Bm  : Wr;

        if (seg > 0) __syncthreads();

        // stage A tile [128 x 64] with tf32 hi/lo split, float4 I/O
        #pragma unroll
        for (int i = tid; i < 2048; i += 256) {     // float4 units
            int r  = i >> 4;
            int k4 = (i & 15) * 4;
            int row = row0 + r;
            float4 v = make_float4(0.f, 0.f, 0.f, 0.f);
            if (row < N) v = *reinterpret_cast<const float4*>(A + (size_t)row * 64 + k4);
            uint4 hi, lo;
            split_tf32(v.x, hi.x, lo.x);
            split_tf32(v.y, hi.y, lo.y);
            split_tf32(v.z, hi.z, lo.z);
            split_tf32(v.w, hi.w, lo.w);
            *reinterpret_cast<uint4*>(&sAhi[r * APAD + k4]) = hi;
            *reinterpret_cast<uint4*>(&sAlo[r * APAD + k4]) = lo;
        }
        // stage W transposed [n*APAD + k] with split
        #pragma unroll
        for (int i = tid; i < 4096; i += 256) {
            int k = i >> 6;
            int n = i & 63;
            uint32_t hi, lo;
            split_tf32(__ldg(W + i), hi, lo);
            sWhi[n * APAD + k] = __uint_as_float(hi);
            sWlo[n * APAD + k] = __uint_as_float(lo);
        }
        __syncthreads();

        #pragma unroll
        for (int kst = 0; kst < 8; kst++) {
            const int k0 = kst * 8;

            uint32_t ahi[2][4], alo[2][4];
            #pragma unroll
            for (int mt = 0; mt < 2; mt++) {
                int r0 = (wm * 32 + mt * 16 + grp) * APAD + k0 + qid;
                int r1 = r0 + 8 * APAD;
                ahi[mt][0] = __float_as_uint(sAhi[r0]);
                ahi[mt][1] = __float_as_uint(sAhi[r1]);
                ahi[mt][2] = __float_as_uint(sAhi[r0 + 4]);
                ahi[mt][3] = __float_as_uint(sAhi[r1 + 4]);
                alo[mt][0] = __float_as_uint(sAlo[r0]);
                alo[mt][1] = __float_as_uint(sAlo[r1]);
                alo[mt][2] = __float_as_uint(sAlo[r0 + 4]);
                alo[mt][3] = __float_as_uint(sAlo[r1 + 4]);
            }
            uint32_t bhi[4][2], blo[4][2];
            #pragma unroll
            for (int nt = 0; nt < 4; nt++) {
                int b0 = (wn * 32 + nt * 8 + grp) * APAD + k0 + qid;
                bhi[nt][0] = __float_as_uint(sWhi[b0]);
                bhi[nt][1] = __float_as_uint(sWhi[b0 + 4]);
                blo[nt][0] = __float_as_uint(sWlo[b0]);
                blo[nt][1] = __float_as_uint(sWlo[b0 + 4]);
            }

            #pragma unroll
            for (int mt = 0; mt < 2; mt++) {
                #pragma unroll
                for (int nt = 0; nt < 4; nt++) {
                    mma_tf32(c[mt][nt], ahi[mt], bhi[nt]);   // hi*hi
                    mma_tf32(c[mt][nt], alo[mt], bhi[nt]);   // lo*hi
                    mma_tf32(c[mt][nt], ahi[mt], blo[nt]);   // hi*lo
                }
            }
        }
    }

    // epilogue: bias + relu + store (c0,c1 = row grp; c2,c3 = row grp+8)
    #pragma unroll
    for (int mt = 0; mt < 2; mt++) {
        int rbase = row0 + wm * 32 + mt * 16 + grp;
        #pragma unroll
        for (int nt = 0; nt < 4; nt++) {
            int col = wn * 32 + nt * 8 + 2 * qid;
            float2 b2 = __ldg(reinterpret_cast<const float2*>(bias + col));
            if (rbase < N) {
                float2 v = make_float2(c[mt][nt][0] + b2.x, c[mt][nt][1] + b2.y);
                if (RELU) { v.x = fmaxf(v.x, 0.f); v.y = fmaxf(v.y, 0.f); }
                *reinterpret_cast<float2*>(H + (size_t)rbase * 64 + col) = v;
            }
            if (rbase + 8 < N) {
                float2 v = make_float2(c[mt][nt][2] + b2.x, c[mt][nt][3] + b2.y);
                if (RELU) { v.x = fmaxf(v.x, 0.f); v.y = fmaxf(v.y, 0.f); }
                *reinterpret_cast<float2*>(H + (size_t)(rbase + 8) * 64 + col) = v;
            }
        }
    }
}

// =================================================================
// Layer 3 + log_softmax fused (unchanged)
// =================================================================
__global__ __launch_bounds__(256) void gemm3_ls(const float* __restrict__ XEp,
                                                const float* __restrict__ X1p,
                                                const float* __restrict__ Xp,
                                                const float* __restrict__ Wm,
                                                const float* __restrict__ Bm,
                                                const float* __restrict__ Wr,
                                                const float* __restrict__ b,
                                                float* __restrict__ OUT, int N)
{
    __shared__ float sw[768];
    int tid = threadIdx.x;
    if (tid < 256) { sw[tid] = Wm[tid]; sw[256 + tid] = Bm[tid]; sw[512 + tid] = Wr[tid]; }
    __syncthreads();

    int row = blockIdx.x * blockDim.x + tid;
    if (row >= N) return;

    float acc[4] = {0.f, 0.f, 0.f, 0.f};
    const float4* xe = reinterpret_cast<const float4*>(XEp + (size_t)row * 64);
    const float4* x1 = reinterpret_cast<const float4*>(X1p + (size_t)row * 64);
    const float4* xp = reinterpret_cast<const float4*>(Xp  + (size_t)row * 64);

    #pragma unroll 4
    for (int k4 = 0; k4 < 16; k4++) {
        float4 ve = __ldg(xe + k4);
        float4 v1 = __ldg(x1 + k4);
        float4 vx = __ldg(xp + k4);
        float es[4] = {ve.x, ve.y, ve.z, ve.w};
        float os[4] = {v1.x, v1.y, v1.z, v1.w};
        float xs[4] = {vx.x, vx.y, vx.z, vx.w};
        #pragma unroll
        for (int j = 0; j < 4; j++) {
            int k = k4 * 4 + j;
            #pragma unroll
            for (int c = 0; c < 4; c++) {
                acc[c] = fmaf(es[j], sw[k * 4 + c], acc[c]);
                acc[c] = fmaf(os[j], sw[256 + k * 4 + c], acc[c]);
                acc[c] = fmaf(xs[j], sw[512 + k * 4 + c], acc[c]);
            }
        }
    }
    #pragma unroll
    for (int c = 0; c < 4; c++) acc[c] += __ldg(b + c);

    float m = fmaxf(fmaxf(acc[0], acc[1]), fmaxf(acc[2], acc[3]));
    float s = __expf(acc[0] - m) + __expf(acc[1] - m) +
              __expf(acc[2] - m) + __expf(acc[3] - m);
    float lse = m + __logf(s);

    float4 o;
    o.x = acc[0] - lse; o.y = acc[1] - lse; o.z = acc[2] - lse; o.w = acc[3] - lse;
    *reinterpret_cast<float4*>(OUT + (size_t)row * 4) = o;
}

// =================================================================
extern "C" void kernel_launch(void* const* d_in, const int* in_sizes, int n_in,
                              void* d_out, int out_size)
{
    const float* x   = (const float*)d_in[0];
    const int*   ei  = (const int*)  d_in[1];
    const float* ea  = (const float*)d_in[2];
    const float* We1 = (const float*)d_in[3];
    const float* be1 = (const float*)d_in[4];
    const float* Wr1 = (const float*)d_in[5];
    const float* b1  = (const float*)d_in[6];
    const float* We2 = (const float*)d_in[7];
    const float* be2 = (const float*)d_in[8];
    const float* Wr2 = (const float*)d_in[9];
    const float* b2  = (const float*)d_in[10];
    const float* We3 = (const float*)d_in[11];
    const float* be3 = (const float*)d_in[12];
    const float* Wr3 = (const float*)d_in[13];
    const float* b3  = (const float*)d_in[14];

    const int N = in_sizes[0] / DIN;
    const int E = in_sizes[2];

    float *XE, *X1, *HA, *HB;
    int *counts, *off, *cursor, *bsum, *boff;
    int2 *meta;
    cudaGetSymbolAddress((void**)&XE, g_XE);
    cudaGetSymbolAddress((void**)&X1, g_X1);
    cudaGetSymbolAddress((void**)&HA, g_HA);
    cudaGetSymbolAddress((void**)&HB, g_HB);
    cudaGetSymbolAddress((void**)&counts, g_counts);
    cudaGetSymbolAddress((void**)&off, g_off);
    cudaGetSymbolAddress((void**)&cursor, g_cursor);
    cudaGetSymbolAddress((void**)&bsum, g_bsum);
    cudaGetSymbolAddress((void**)&boff, g_boff);
    cudaGetSymbolAddress((void**)&meta, g_meta);
    float* OUT = (float*)d_out;

    cudaFuncSetAttribute(gemm192_tc<true>, cudaFuncAttributeMaxDynamicSharedMemorySize, TC_SMEM_BYTES);

    const int edgeGrid = (E + 255) / 256;
    const int rowGrid  = (N + 255) / 256;
    const int aggGrid  = (N * 32 + 255) / 256;
    const int tcGrid   = (N + 127) / 128;
    const int scanGrid = (N + 2047) / 2048;

    // ---- CSR build (reused by all 3 layers) ----
    zero_kernel<<<rowGrid, 256>>>(counts, N);
    hist_kernel<<<edgeGrid, 256>>>(ei, counts, E);
    scanA_kernel<<<scanGrid, 256>>>(counts, bsum, N);
    scanB_kernel<<<1, 64>>>(bsum, boff, off, scanGrid, N);
    scanC_kernel<<<scanGrid, 256>>>(counts, boff, off, cursor, N);
    scatter_kernel<<<edgeGrid, 256>>>(ei, ea, cursor, meta, E);

    // ---- layer 1 ----
    aggx_kernel<<<aggGrid, 256>>>(off, meta, x, XE, X1, N);
    gemm192_tc<true><<<tcGrid, 256, TC_SMEM_BYTES>>>(XE, X1, x, We1, be1, Wr1, b1, HA, N);

    // ---- layer 2 ----
    aggx_kernel<<<aggGrid, 256>>>(off, meta, HA, XE, X1, N);
    gemm192_tc<true><<<tcGrid, 256, TC_SMEM_BYTES>>>(XE, X1, HA, We2, be2, Wr2, b2, HB, N);

    // ---- layer 3 ----
    aggx_kernel<<<aggGrid, 256>>>(off, meta, HB, XE, X1, N);
    gemm3_ls<<<rowGrid, 256>>>(XE, X1, HB, We3, be3, Wr3, b3, OUT, N);
}

// round 9
// speedup vs baseline: 1.8827x; 1.0558x over previous
#include <cuda_runtime.h>
#include <cstdint>

#define MAXN 100000
#define MAXE 1600000
#define DIN  64

// ---------------- scratch (no cudaMalloc allowed) ----------------
__device__ float g_XE[(size_t)MAXN * 64];   // sum of e * X[src] per dst
__device__ float g_X1[(size_t)MAXN * 64];   // sum of X[src] per dst
__device__ float g_HA[(size_t)MAXN * 64];   // relu(layer1 out)
__device__ float g_HB[(size_t)MAXN * 64];   // relu(layer2 out)
__device__ int   g_counts[MAXN];
__device__ int   g_off[MAXN + 1];
__device__ int   g_cursor[MAXN];
__device__ int   g_bsum[64];
__device__ int   g_boff[64];
__device__ int2  g_meta[MAXE];              // {src, bits(e)} grouped by dst

// pre-split tf32 weights: [mat 0..8][hi/lo][n*68+k], mat = layer*3 + seg
#define APAD 68
#define WSEG_FLOATS (64 * APAD)             /* 4352 */
__device__ float g_Wsp[9 * 2 * WSEG_FLOATS];

// =================================================================
// CSR build (unchanged from R7/R8 winner)
// =================================================================
__global__ void zero_kernel(int* __restrict__ counts, int N)
{
    int i = blockIdx.x * blockDim.x + threadIdx.x;
    if (i < N) counts[i] = 0;
}

__global__ void hist_kernel(const int* __restrict__ ei, int* __restrict__ counts, int E)
{
    int e = blockIdx.x * blockDim.x + threadIdx.x;
    if (e < E) atomicAdd(&counts[__ldg(ei + E + e)], 1);
}

__global__ __launch_bounds__(256) void scanA_kernel(const int* __restrict__ counts,
                                                    int* __restrict__ bsum, int N)
{
    __shared__ int red[256];
    int tid = threadIdx.x;
    int base = blockIdx.x * 2048 + tid * 8;
    int s = 0;
    if (base < N) {
        int4 a = *reinterpret_cast<const int4*>(counts + base);
        int4 b = *reinterpret_cast<const int4*>(counts + base + 4);
        s = a.x + a.y + a.z + a.w + b.x + b.y + b.z + b.w;
    }
    red[tid] = s;
    __syncthreads();
    #pragma unroll
    for (int d = 128; d > 0; d >>= 1) {
        if (tid < d) red[tid] += red[tid + d];
        __syncthreads();
    }
    if (tid == 0) bsum[blockIdx.x] = red[0];
}

__global__ __launch_bounds__(64) void scanB_kernel(const int* __restrict__ bsum,
                                                   int* __restrict__ boff,
                                                   int* __restrict__ off, int B, int N)
{
    __shared__ int sh[64];
    int tid = threadIdx.x;
    int v = (tid < B) ? bsum[tid] : 0;
    sh[tid] = v;
    __syncthreads();
    #pragma unroll
    for (int d = 1; d < 64; d <<= 1) {
        int t = (tid >= d) ? sh[tid - d] : 0;
        __syncthreads();
        sh[tid] += t;
        __syncthreads();
    }
    boff[tid] = sh[tid] - v;
    if (tid == 63) off[N] = sh[63];
}

__global__ __launch_bounds__(256) void scanC_kernel(const int* __restrict__ counts,
                                                    const int* __restrict__ boff,
                                                    int* __restrict__ off,
                                                    int* __restrict__ cursor, int N)
{
    __shared__ int wsum[8], woff[8];
    int tid = threadIdx.x;
    int lane = tid & 31;
    int warp = tid >> 5;
    int base = blockIdx.x * 2048 + tid * 8;

    int4 a = make_int4(0, 0, 0, 0), b = make_int4(0, 0, 0, 0);
    if (base < N) {
        a = *reinterpret_cast<const int4*>(counts + base);
        b = *reinterpret_cast<const int4*>(counts + base + 4);
    }
    int s = a.x + a.y + a.z + a.w + b.x + b.y + b.z + b.w;

    int incl = s;
    #pragma unroll
    for (int d = 1; d < 32; d <<= 1) {
        int t = __shfl_up_sync(0xFFFFFFFFu, incl, d);
        if (lane >= d) incl += t;
    }
    if (lane == 31) wsum[warp] = incl;
    __syncthreads();
    if (tid == 0) {
        int run = 0;
        #pragma unroll
        for (int j = 0; j < 8; j++) { int t = wsum[j]; woff[j] = run; run += t; }
    }
    __syncthreads();

    int ex = __ldg(boff + blockIdx.x) + woff[warp] + (incl - s);
    if (base < N) {
        int o0 = ex;
        int o1 = o0 + a.x, o2 = o1 + a.y, o3 = o2 + a.z, o4 = o3 + a.w;
        int o5 = o4 + b.x, o6 = o5 + b.y, o7 = o6 + b.z;
        int4 oa = make_int4(o0, o1, o2, o3);
        int4 ob = make_int4(o4, o5, o6, o7);
        *reinterpret_cast<int4*>(off + base)        = oa;
        *reinterpret_cast<int4*>(off + base + 4)    = ob;
        *reinterpret_cast<int4*>(cursor + base)     = oa;
        *reinterpret_cast<int4*>(cursor + base + 4) = ob;
    }
}

__global__ void scatter_kernel(const int* __restrict__ ei, const float* __restrict__ ea,
                               int* __restrict__ cursor, int2* __restrict__ meta, int E)
{
    int e = blockIdx.x * blockDim.x + threadIdx.x;
    if (e >= E) return;
    int s = __ldg(ei + e);
    int d = __ldg(ei + E + e);
    int pos = atomicAdd(&cursor[d], 1);
    meta[pos] = make_int2(s, __float_as_int(__ldg(ea + e)));
}

// =================================================================
// tf32 split helpers
// =================================================================
__device__ __forceinline__ void split_tf32(float v, uint32_t& hi, uint32_t& lo)
{
    asm("cvt.rna.tf32.f32 %0, %1;" : "=r"(hi) : "f"(v));
    float r = v - __uint_as_float(hi);
    asm("cvt.rna.tf32.f32 %0, %1;" : "=r"(lo) : "f"(r));
}

// Pre-split all 9 weight matrices into global padded layout.
// mat = layer*3 + seg; input [k*64+n] row-major; output [n*APAD+k] hi, lo.
__global__ __launch_bounds__(256) void presplit_kernel(
    const float* __restrict__ m0, const float* __restrict__ m1, const float* __restrict__ m2,
    const float* __restrict__ m3, const float* __restrict__ m4, const float* __restrict__ m5,
    const float* __restrict__ m6, const float* __restrict__ m7, const float* __restrict__ m8,
    float* __restrict__ out)
{
    int idx = blockIdx.x * blockDim.x + threadIdx.x;
    if (idx >= 9 * 4096) return;
    int mat = idx >> 12;
    int j = idx & 4095;
    int k = j >> 6;
    int n = j & 63;

    const float* src;
    switch (mat) {
        case 0: src = m0; break; case 1: src = m1; break; case 2: src = m2; break;
        case 3: src = m3; break; case 4: src = m4; break; case 5: src = m5; break;
        case 6: src = m6; break; case 7: src = m7; break; default: src = m8; break;
    }
    uint32_t hi, lo;
    split_tf32(__ldg(src + j), hi, lo);
    float* dst = out + (size_t)mat * 2 * WSEG_FLOATS;
    dst[n * APAD + k]               = __uint_as_float(hi);
    dst[WSEG_FLOATS + n * APAD + k] = __uint_as_float(lo);
}

// =================================================================
// Feature-space aggregation (measured 42us — unchanged)
// =================================================================
__global__ __launch_bounds__(256) void aggx_kernel(const int* __restrict__ off,
                                                   const int2* __restrict__ meta,
                                                   const float* __restrict__ X,
                                                   float* __restrict__ XE,
                                                   float* __restrict__ X1, int N)
{
    int w = (blockIdx.x * blockDim.x + threadIdx.x) >> 5;
    int lane = threadIdx.x & 31;
    if (w >= N) return;

    int beg = __ldg(off + w);
    int end = __ldg(off + w + 1);

    float2 aE = make_float2(0.f, 0.f);
    float2 a1 = make_float2(0.f, 0.f);

    int k = beg;
    for (; k + 2 <= end; k += 2) {
        int2 m0 = __ldg(meta + k);
        int2 m1 = __ldg(meta + k + 1);
        float2 v0 = *reinterpret_cast<const float2*>(X + (size_t)m0.x * 64 + lane * 2);
        float2 v1 = *reinterpret_cast<const float2*>(X + (size_t)m1.x * 64 + lane * 2);
        float e0 = __int_as_float(m0.y);
        float e1 = __int_as_float(m1.y);
        aE.x = fmaf(e0, v0.x, aE.x); aE.y = fmaf(e0, v0.y, aE.y);
        aE.x = fmaf(e1, v1.x, aE.x); aE.y = fmaf(e1, v1.y, aE.y);
        a1.x += v0.x + v1.x;         a1.y += v0.y + v1.y;
    }
    if (k < end) {
        int2 m0 = __ldg(meta + k);
        float2 v0 = *reinterpret_cast<const float2*>(X + (size_t)m0.x * 64 + lane * 2);
        float e0 = __int_as_float(m0.y);
        aE.x = fmaf(e0, v0.x, aE.x); aE.y = fmaf(e0, v0.y, aE.y);
        a1.x += v0.x;                a1.y += v0.y;
    }

    *reinterpret_cast<float2*>(XE + (size_t)w * 64 + lane * 2) = aE;
    *reinterpret_cast<float2*>(X1 + (size_t)w * 64 + lane * 2) = a1;
}

// =================================================================
// 3xTF32 tensor-core GEMM with pre-split weights:
// H = relu?(XE@Wm + X1@Bm + X@Wr + b)
// =================================================================
#define SA_FLOATS (128 * APAD)     /* 8704  */
#define TC_SMEM_FLOATS (2 * SA_FLOATS + 2 * WSEG_FLOATS)
#define TC_SMEM_BYTES  (TC_SMEM_FLOATS * 4)   /* 104448 B */

__device__ __forceinline__ void mma_tf32(float* c, const uint32_t* a, const uint32_t* b)
{
    asm("mma.sync.aligned.m16n8k8.row.col.f32.tf32.tf32.f32 "
        "{%0,%1,%2,%3}, {%4,%5,%6,%7}, {%8,%9}, {%0,%1,%2,%3};"
        : "+f"(c[0]), "+f"(c[1]), "+f"(c[2]), "+f"(c[3])
        : "r"(a[0]), "r"(a[1]), "r"(a[2]), "r"(a[3]), "r"(b[0]), "r"(b[1]));
}

template<bool RELU>
__global__ __launch_bounds__(256, 2) void gemm192_tc(const float* __restrict__ XEp,
                                                     const float* __restrict__ X1p,
                                                     const float* __restrict__ Xp,
                                                     const float* __restrict__ Wsp,
                                                     const float* __restrict__ bias,
                                                     float* __restrict__ H, int N)
{
    extern __shared__ float sm[];
    float* sAhi = sm;                       // [row*APAD + k], 128x64
    float* sAlo = sAhi + SA_FLOATS;
    float* sWhi = sAlo + SA_FLOATS;         // [n*APAD + k], 64x64
    float* sWlo = sWhi + WSEG_FLOATS;

    const int tid  = threadIdx.x;
    const int lane = tid & 31;
    const int wid  = tid >> 5;
    const int grp  = lane >> 2;             // 0..7
    const int qid  = lane & 3;              // 0..3
    const int wm   = wid & 3;               // warp row 0..3 -> rows wm*32
    const int wn   = wid >> 2;              // warp col 0..1 -> cols wn*32
    const int row0 = blockIdx.x * 128;

    float c[2][4][4];
    #pragma unroll
    for (int mt = 0; mt < 2; mt++)
        #pragma unroll
        for (int nt = 0; nt < 4; nt++)
            #pragma unroll
            for (int j = 0; j < 4; j++) c[mt][nt][j] = 0.f;

    #pragma unroll
    for (int seg = 0; seg < 3; seg++) {
        const float* A = (seg == 0) ? XEp : (seg == 1) ? X1p : Xp;
        const float* Wseg = Wsp + (size_t)seg * 2 * WSEG_FLOATS;

        if (seg > 0) __syncthreads();

        // stage A tile [128 x 64] with tf32 hi/lo split, float4 I/O
        #pragma unroll
        for (int i = tid; i < 2048; i += 256) {
            int r  = i >> 4;
            int k4 = (i & 15) * 4;
            int row = row0 + r;
            float4 v = make_float4(0.f, 0.f, 0.f, 0.f);
            if (row < N) v = *reinterpret_cast<const float4*>(A + (size_t)row * 64 + k4);
            uint4 hi, lo;
            split_tf32(v.x, hi.x, lo.x);
            split_tf32(v.y, hi.y, lo.y);
            split_tf32(v.z, hi.z, lo.z);
            split_tf32(v.w, hi.w, lo.w);
            *reinterpret_cast<uint4*>(&sAhi[r * APAD + k4]) = hi;
            *reinterpret_cast<uint4*>(&sAlo[r * APAD + k4]) = lo;
        }
        // stage pre-split W: straight float4 copy (coalesced, conflict-free)
        #pragma unroll
        for (int i = tid; i < 2176; i += 256) {
            float4 v = __ldg(reinterpret_cast<const float4*>(Wseg) + i);
            *reinterpret_cast<float4*>(&sWhi[i * 4]) = v;   // sWhi..sWlo contiguous
        }
        __syncthreads();

        #pragma unroll
        for (int kst = 0; kst < 8; kst++) {
            const int k0 = kst * 8;

            uint32_t ahi[2][4], alo[2][4];
            #pragma unroll
            for (int mt = 0; mt < 2; mt++) {
                int r0 = (wm * 32 + mt * 16 + grp) * APAD + k0 + qid;
                int r1 = r0 + 8 * APAD;
                ahi[mt][0] = __float_as_uint(sAhi[r0]);
                ahi[mt][1] = __float_as_uint(sAhi[r1]);
                ahi[mt][2] = __float_as_uint(sAhi[r0 + 4]);
                ahi[mt][3] = __float_as_uint(sAhi[r1 + 4]);
                alo[mt][0] = __float_as_uint(sAlo[r0]);
                alo[mt][1] = __float_as_uint(sAlo[r1]);
                alo[mt][2] = __float_as_uint(sAlo[r0 + 4]);
                alo[mt][3] = __float_as_uint(sAlo[r1 + 4]);
            }
            uint32_t bhi[4][2], blo[4][2];
            #pragma unroll
            for (int nt = 0; nt < 4; nt++) {
                int b0 = (wn * 32 + nt * 8 + grp) * APAD + k0 + qid;
                bhi[nt][0] = __float_as_uint(sWhi[b0]);
                bhi[nt][1] = __float_as_uint(sWhi[b0 + 4]);
                blo[nt][0] = __float_as_uint(sWlo[b0]);
                blo[nt][1] = __float_as_uint(sWlo[b0 + 4]);
            }

            #pragma unroll
            for (int mt = 0; mt < 2; mt++) {
                #pragma unroll
                for (int nt = 0; nt < 4; nt++) {
                    mma_tf32(c[mt][nt], ahi[mt], bhi[nt]);
                    mma_tf32(c[mt][nt], alo[mt], bhi[nt]);
                    mma_tf32(c[mt][nt], ahi[mt], blo[nt]);
                }
            }
        }
    }

    #pragma unroll
    for (int mt = 0; mt < 2; mt++) {
        int rbase = row0 + wm * 32 + mt * 16 + grp;
        #pragma unroll
        for (int nt = 0; nt < 4; nt++) {
            int col = wn * 32 + nt * 8 + 2 * qid;
            float2 b2 = __ldg(reinterpret_cast<const float2*>(bias + col));
            if (rbase < N) {
                float2 v = make_float2(c[mt][nt][0] + b2.x, c[mt][nt][1] + b2.y);
                if (RELU) { v.x = fmaxf(v.x, 0.f); v.y = fmaxf(v.y, 0.f); }
                *reinterpret_cast<float2*>(H + (size_t)rbase * 64 + col) = v;
            }
            if (rbase + 8 < N) {
                float2 v = make_float2(c[mt][nt][2] + b2.x, c[mt][nt][3] + b2.y);
                if (RELU) { v.x = fmaxf(v.x, 0.f); v.y = fmaxf(v.y, 0.f); }
                *reinterpret_cast<float2*>(H + (size_t)(rbase + 8) * 64 + col) = v;
            }
        }
    }
}

// =================================================================
// Layer 3 fully fused: warp-per-node gather + 64->4 projection +
// butterfly reduce + log_softmax.  out = logsm(aE@Wm3 + a1@Bm3 + HB@Wr3 + b3)
// =================================================================
__global__ __launch_bounds__(256) void agg3_ls(const int* __restrict__ off,
                                               const int2* __restrict__ meta,
                                               const float* __restrict__ HBp,
                                               const float* __restrict__ Wm,
                                               const float* __restrict__ Bm,
                                               const float* __restrict__ Wr,
                                               const float* __restrict__ b,
                                               float* __restrict__ OUT, int N)
{
    __shared__ float sw[768];   // [0:256) Wm, [256:512) Bm, [512:768) Wr  layout k*4+c
    int tid = threadIdx.x;
    if (tid < 256) { sw[tid] = Wm[tid]; sw[256 + tid] = Bm[tid]; sw[512 + tid] = Wr[tid]; }
    __syncthreads();

    int w = (blockIdx.x * blockDim.x + tid) >> 5;
    int lane = tid & 31;
    if (w >= N) return;

    int beg = __ldg(off + w);
    int end = __ldg(off + w + 1);

    float2 aE = make_float2(0.f, 0.f);
    float2 a1 = make_float2(0.f, 0.f);

    int k = beg;
    for (; k + 2 <= end; k += 2) {
        int2 m0 = __ldg(meta + k);
        int2 m1 = __ldg(meta + k + 1);
        float2 v0 = *reinterpret_cast<const float2*>(HBp + (size_t)m0.x * 64 + lane * 2);
        float2 v1 = *reinterpret_cast<const float2*>(HBp + (size_t)m1.x * 64 + lane * 2);
        float e0 = __int_as_float(m0.y);
        float e1 = __int_as_float(m1.y);
        aE.x = fmaf(e0, v0.x, aE.x); aE.y = fmaf(e0, v0.y, aE.y);
        aE.x = fmaf(e1, v1.x, aE.x); aE.y = fmaf(e1, v1.y, aE.y);
        a1.x += v0.x + v1.x;         a1.y += v0.y + v1.y;
    }
    if (k < end) {
        int2 m0 = __ldg(meta + k);
        float2 v0 = *reinterpret_cast<const float2*>(HBp + (size_t)m0.x * 64 + lane * 2);
        float e0 = __int_as_float(m0.y);
        aE.x = fmaf(e0, v0.x, aE.x); aE.y = fmaf(e0, v0.y, aE.y);
        a1.x += v0.x;                a1.y += v0.y;
    }

    // own-row values for the root term
    float2 hb = *reinterpret_cast<const float2*>(HBp + (size_t)w * 64 + lane * 2);

    const int k0 = lane * 2 * 4;       // sw index of channel 2*lane, col 0
    float p[4];
    #pragma unroll
    for (int c = 0; c < 4; c++) {
        float v = aE.x * sw[k0 + c] + aE.y * sw[k0 + 4 + c];
        v = fmaf(a1.x, sw[256 + k0 + c], v);
        v = fmaf(a1.y, sw[256 + k0 + 4 + c], v);
        v = fmaf(hb.x, sw[512 + k0 + c], v);
        v = fmaf(hb.y, sw[512 + k0 + 4 + c], v);
        p[c] = v;
    }
    #pragma unroll
    for (int d = 16; d > 0; d >>= 1) {
        p[0] += __shfl_xor_sync(0xFFFFFFFFu, p[0], d);
        p[1] += __shfl_xor_sync(0xFFFFFFFFu, p[1], d);
        p[2] += __shfl_xor_sync(0xFFFFFFFFu, p[2], d);
        p[3] += __shfl_xor_sync(0xFFFFFFFFu, p[3], d);
    }

    if (lane == 0) {
        #pragma unroll
        for (int c = 0; c < 4; c++) p[c] += __ldg(b + c);
        float m = fmaxf(fmaxf(p[0], p[1]), fmaxf(p[2], p[3]));
        float s = __expf(p[0] - m) + __expf(p[1] - m) +
                  __expf(p[2] - m) + __expf(p[3] - m);
        float lse = m + __logf(s);
        float4 o;
        o.x = p[0] - lse; o.y = p[1] - lse; o.z = p[2] - lse; o.w = p[3] - lse;
        *reinterpret_cast<float4*>(OUT + (size_t)w * 4) = o;
    }
}

// =================================================================
extern "C" void kernel_launch(void* const* d_in, const int* in_sizes, int n_in,
                              void* d_out, int out_size)
{
    const float* x   = (const float*)d_in[0];
    const int*   ei  = (const int*)  d_in[1];
    const float* ea  = (const float*)d_in[2];
    const float* We1 = (const float*)d_in[3];
    const float* be1 = (const float*)d_in[4];
    const float* Wr1 = (const float*)d_in[5];
    const float* b1  = (const float*)d_in[6];
    const float* We2 = (const float*)d_in[7];
    const float* be2 = (const float*)d_in[8];
    const float* Wr2 = (const float*)d_in[9];
    const float* b2  = (const float*)d_in[10];
    const float* We3 = (const float*)d_in[11];
    const float* be3 = (const float*)d_in[12];
    const float* Wr3 = (const float*)d_in[13];
    const float* b3  = (const float*)d_in[14];

    const int N = in_sizes[0] / DIN;
    const int E = in_sizes[2];

    float *XE, *X1, *HA, *HB, *Wsp;
    int *counts, *off, *cursor, *bsum, *boff;
    int2 *meta;
    cudaGetSymbolAddress((void**)&XE, g_XE);
    cudaGetSymbolAddress((void**)&X1, g_X1);
    cudaGetSymbolAddress((void**)&HA, g_HA);
    cudaGetSymbolAddress((void**)&HB, g_HB);
    cudaGetSymbolAddress((void**)&Wsp, g_Wsp);
    cudaGetSymbolAddress((void**)&counts, g_counts);
    cudaGetSymbolAddress((void**)&off, g_off);
    cudaGetSymbolAddress((void**)&cursor, g_cursor);
    cudaGetSymbolAddress((void**)&bsum, g_bsum);
    cudaGetSymbolAddress((void**)&boff, g_boff);
    cudaGetSymbolAddress((void**)&meta, g_meta);
    float* OUT = (float*)d_out;

    cudaFuncSetAttribute(gemm192_tc<true>, cudaFuncAttributeMaxDynamicSharedMemorySize, TC_SMEM_BYTES);

    const int edgeGrid = (E + 255) / 256;
    const int rowGrid  = (N + 255) / 256;
    const int aggGrid  = (N * 32 + 255) / 256;
    const int tcGrid   = (N + 127) / 128;
    const int scanGrid = (N + 2047) / 2048;

    // ---- CSR build + weight pre-split ----
    zero_kernel<<<rowGrid, 256>>>(counts, N);
    hist_kernel<<<edgeGrid, 256>>>(ei, counts, E);
    scanA_kernel<<<scanGrid, 256>>>(counts, bsum, N);
    scanB_kernel<<<1, 64>>>(bsum, boff, off, scanGrid, N);
    scanC_kernel<<<scanGrid, 256>>>(counts, boff, off, cursor, N);
    scatter_kernel<<<edgeGrid, 256>>>(ei, ea, cursor, meta, E);
    presplit_kernel<<<144, 256>>>(We1, be1, Wr1, We2, be2, Wr2, We3, be3, Wr3, Wsp);

    // ---- layer 1 ----
    aggx_kernel<<<aggGrid, 256>>>(off, meta, x, XE, X1, N);
    gemm192_tc<true><<<tcGrid, 256, TC_SMEM_BYTES>>>(XE, X1, x, Wsp, b1, HA, N);

    // ---- layer 2 ----
    aggx_kernel<<<aggGrid, 256>>>(off, meta, HA, XE, X1, N);
    gemm192_tc<true><<<tcGrid, 256, TC_SMEM_BYTES>>>(XE, X1, HA,
                                                     Wsp + (size_t)3 * 2 * WSEG_FLOATS, b2, HB, N);

    // ---- layer 3 (fully fused) ----
    agg3_ls<<<aggGrid, 256>>>(off, meta, HB, We3, be3, Wr3, b3, OUT, N);
}

// round 10
// speedup vs baseline: 1.8962x; 1.0071x over previous
#include <cuda_runtime.h>
#include <cuda_fp16.h>
#include <cstdint>

#define MAXN 100000
#define MAXE 1600000
#define DIN  64

// ---------------- scratch (no cudaMalloc allowed) ----------------
__device__ float  g_XE[(size_t)MAXN * 64];   // sum of e * X[src] per dst (fp32)
__device__ float  g_X1[(size_t)MAXN * 64];   // sum of X[src] per dst (fp32)
__device__ __half g_Xh[(size_t)MAXN * 64];   // fp16 copy of input x
__device__ __half g_HAh[(size_t)MAXN * 64];  // relu(layer1 out), fp16
__device__ __half g_HBh[(size_t)MAXN * 64];  // relu(layer2 out), fp16
__device__ int    g_counts[MAXN];
__device__ int    g_off[MAXN + 1];
__device__ int    g_cursor[MAXN];
__device__ int    g_bsum[64];
__device__ int    g_boff[64];
__device__ int2   g_meta[MAXE];              // {src, bits(e)} grouped by dst

// pre-split tf32 weights: [mat 0..8][hi/lo][n*68+k]
#define APAD 68
#define WSEG_FLOATS (64 * APAD)              /* 4352 */
__device__ float g_Wsp[9 * 2 * WSEG_FLOATS];

// =================================================================
// CSR build (unchanged — measured components)
// =================================================================
__global__ void zero_kernel(int* __restrict__ counts, int N)
{
    int i = blockIdx.x * blockDim.x + threadIdx.x;
    if (i < N) counts[i] = 0;
}

__global__ void hist_kernel(const int* __restrict__ ei, int* __restrict__ counts, int E)
{
    int e = blockIdx.x * blockDim.x + threadIdx.x;
    if (e < E) atomicAdd(&counts[__ldg(ei + E + e)], 1);
}

__global__ __launch_bounds__(256) void scanA_kernel(const int* __restrict__ counts,
                                                    int* __restrict__ bsum, int N)
{
    __shared__ int red[256];
    int tid = threadIdx.x;
    int base = blockIdx.x * 2048 + tid * 8;
    int s = 0;
    if (base < N) {
        int4 a = *reinterpret_cast<const int4*>(counts + base);
        int4 b = *reinterpret_cast<const int4*>(counts + base + 4);
        s = a.x + a.y + a.z + a.w + b.x + b.y + b.z + b.w;
    }
    red[tid] = s;
    __syncthreads();
    #pragma unroll
    for (int d = 128; d > 0; d >>= 1) {
        if (tid < d) red[tid] += red[tid + d];
        __syncthreads();
    }
    if (tid == 0) bsum[blockIdx.x] = red[0];
}

__global__ __launch_bounds__(64) void scanB_kernel(const int* __restrict__ bsum,
                                                   int* __restrict__ boff,
                                                   int* __restrict__ off, int B, int N)
{
    __shared__ int sh[64];
    int tid = threadIdx.x;
    int v = (tid < B) ? bsum[tid] : 0;
    sh[tid] = v;
    __syncthreads();
    #pragma unroll
    for (int d = 1; d < 64; d <<= 1) {
        int t = (tid >= d) ? sh[tid - d] : 0;
        __syncthreads();
        sh[tid] += t;
        __syncthreads();
    }
    boff[tid] = sh[tid] - v;
    if (tid == 63) off[N] = sh[63];
}

__global__ __launch_bounds__(256) void scanC_kernel(const int* __restrict__ counts,
                                                    const int* __restrict__ boff,
                                                    int* __restrict__ off,
                                                    int* __restrict__ cursor, int N)
{
    __shared__ int wsum[8], woff[8];
    int tid = threadIdx.x;
    int lane = tid & 31;
    int warp = tid >> 5;
    int base = blockIdx.x * 2048 + tid * 8;

    int4 a = make_int4(0, 0, 0, 0), b = make_int4(0, 0, 0, 0);
    if (base < N) {
        a = *reinterpret_cast<const int4*>(counts + base);
        b = *reinterpret_cast<const int4*>(counts + base + 4);
    }
    int s = a.x + a.y + a.z + a.w + b.x + b.y + b.z + b.w;

    int incl = s;
    #pragma unroll
    for (int d = 1; d < 32; d <<= 1) {
        int t = __shfl_up_sync(0xFFFFFFFFu, incl, d);
        if (lane >= d) incl += t;
    }
    if (lane == 31) wsum[warp] = incl;
    __syncthreads();
    if (tid == 0) {
        int run = 0;
        #pragma unroll
        for (int j = 0; j < 8; j++) { int t = wsum[j]; woff[j] = run; run += t; }
    }
    __syncthreads();

    int ex = __ldg(boff + blockIdx.x) + woff[warp] + (incl - s);
    if (base < N) {
        int o0 = ex;
        int o1 = o0 + a.x, o2 = o1 + a.y, o3 = o2 + a.z, o4 = o3 + a.w;
        int o5 = o4 + b.x, o6 = o5 + b.y, o7 = o6 + b.z;
        int4 oa = make_int4(o0, o1, o2, o3);
        int4 ob = make_int4(o4, o5, o6, o7);
        *reinterpret_cast<int4*>(off + base)        = oa;
        *reinterpret_cast<int4*>(off + base + 4)    = ob;
        *reinterpret_cast<int4*>(cursor + base)     = oa;
        *reinterpret_cast<int4*>(cursor + base + 4) = ob;
    }
}

__global__ void scatter_kernel(const int* __restrict__ ei, const float* __restrict__ ea,
                               int* __restrict__ cursor, int2* __restrict__ meta, int E)
{
    int e = blockIdx.x * blockDim.x + threadIdx.x;
    if (e >= E) return;
    int s = __ldg(ei + e);
    int d = __ldg(ei + E + e);
    int pos = atomicAdd(&cursor[d], 1);
    meta[pos] = make_int2(s, __float_as_int(__ldg(ea + e)));
}

// =================================================================
// tf32 split + weight pre-split (unchanged)
// =================================================================
__device__ __forceinline__ void split_tf32(float v, uint32_t& hi, uint32_t& lo)
{
    asm("cvt.rna.tf32.f32 %0, %1;" : "=r"(hi) : "f"(v));
    float r = v - __uint_as_float(hi);
    asm("cvt.rna.tf32.f32 %0, %1;" : "=r"(lo) : "f"(r));
}

__global__ __launch_bounds__(256) void presplit_kernel(
    const float* __restrict__ m0, const float* __restrict__ m1, const float* __restrict__ m2,
    const float* __restrict__ m3, const float* __restrict__ m4, const float* __restrict__ m5,
    const float* __restrict__ m6, const float* __restrict__ m7, const float* __restrict__ m8,
    float* __restrict__ out)
{
    int idx = blockIdx.x * blockDim.x + threadIdx.x;
    if (idx >= 9 * 4096) return;
    int mat = idx >> 12;
    int j = idx & 4095;
    int k = j >> 6;
    int n = j & 63;

    const float* src;
    switch (mat) {
        case 0: src = m0; break; case 1: src = m1; break; case 2: src = m2; break;
        case 3: src = m3; break; case 4: src = m4; break; case 5: src = m5; break;
        case 6: src = m6; break; case 7: src = m7; break; default: src = m8; break;
    }
    uint32_t hi, lo;
    split_tf32(__ldg(src + j), hi, lo);
    float* dst = out + (size_t)mat * 2 * WSEG_FLOATS;
    dst[n * APAD + k]               = __uint_as_float(hi);
    dst[WSEG_FLOATS + n * APAD + k] = __uint_as_float(lo);
}

// =================================================================
// x -> fp16 conversion (one-time)
// =================================================================
__global__ __launch_bounds__(256) void cvt_half_kernel(const float* __restrict__ X,
                                                       __half* __restrict__ Xh, int total)
{
    int i = blockIdx.x * blockDim.x + threadIdx.x;     // 8 elems per thread
    int base = i * 8;
    if (base >= total) return;
    float4 a = *reinterpret_cast<const float4*>(X + base);
    float4 b = *reinterpret_cast<const float4*>(X + base + 4);
    __half2 h[4];
    h[0] = __float22half2_rn(make_float2(a.x, a.y));
    h[1] = __float22half2_rn(make_float2(a.z, a.w));
    h[2] = __float22half2_rn(make_float2(b.x, b.y));
    h[3] = __float22half2_rn(make_float2(b.z, b.w));
    *reinterpret_cast<uint4*>(Xh + base) = *reinterpret_cast<uint4*>(h);
}

// =================================================================
// fp16-gather aggregation: XE[i]=sum e*X[s], X1[i]=sum X[s]
// warp per node, lane owns 2 channels (one half2 = 4B per edge)
// =================================================================
__global__ __launch_bounds__(256) void aggx_h_kernel(const int* __restrict__ off,
                                                     const int2* __restrict__ meta,
                                                     const __half* __restrict__ Xh,
                                                     float* __restrict__ XE,
                                                     float* __restrict__ X1, int N)
{
    int w = (blockIdx.x * blockDim.x + threadIdx.x) >> 5;
    int lane = threadIdx.x & 31;
    if (w >= N) return;

    int beg = __ldg(off + w);
    int end = __ldg(off + w + 1);

    float2 aE = make_float2(0.f, 0.f);
    float2 a1 = make_float2(0.f, 0.f);

    const __half2* X2 = reinterpret_cast<const __half2*>(Xh);

    int k = beg;
    for (; k + 2 <= end; k += 2) {
        int2 m0 = __ldg(meta + k);
        int2 m1 = __ldg(meta + k + 1);
        float2 v0 = __half22float2(X2[(size_t)m0.x * 32 + lane]);
        float2 v1 = __half22float2(X2[(size_t)m1.x * 32 + lane]);
        float e0 = __int_as_float(m0.y);
        float e1 = __int_as_float(m1.y);
        aE.x = fmaf(e0, v0.x, aE.x); aE.y = fmaf(e0, v0.y, aE.y);
        aE.x = fmaf(e1, v1.x, aE.x); aE.y = fmaf(e1, v1.y, aE.y);
        a1.x += v0.x + v1.x;         a1.y += v0.y + v1.y;
    }
    if (k < end) {
        int2 m0 = __ldg(meta + k);
        float2 v0 = __half22float2(X2[(size_t)m0.x * 32 + lane]);
        float e0 = __int_as_float(m0.y);
        aE.x = fmaf(e0, v0.x, aE.x); aE.y = fmaf(e0, v0.y, aE.y);
        a1.x += v0.x;                a1.y += v0.y;
    }

    *reinterpret_cast<float2*>(XE + (size_t)w * 64 + lane * 2) = aE;
    *reinterpret_cast<float2*>(X1 + (size_t)w * 64 + lane * 2) = a1;
}

// =================================================================
// 3xTF32 tensor-core GEMM, X-seg from fp16, fp16 output:
// Hh = relu(XE@Wm + X1@Bm + X@Wr + b)  (fp16 store)
// =================================================================
#define SA_FLOATS (128 * APAD)     /* 8704  */
#define TC_SMEM_FLOATS (2 * SA_FLOATS + 2 * WSEG_FLOATS)
#define TC_SMEM_BYTES  (TC_SMEM_FLOATS * 4)   /* 104448 B */

__device__ __forceinline__ void mma_tf32(float* c, const uint32_t* a, const uint32_t* b)
{
    asm("mma.sync.aligned.m16n8k8.row.col.f32.tf32.tf32.f32 "
        "{%0,%1,%2,%3}, {%4,%5,%6,%7}, {%8,%9}, {%0,%1,%2,%3};"
        : "+f"(c[0]), "+f"(c[1]), "+f"(c[2]), "+f"(c[3])
        : "r"(a[0]), "r"(a[1]), "r"(a[2]), "r"(a[3]), "r"(b[0]), "r"(b[1]));
}

__global__ __launch_bounds__(256, 2) void gemm192_tc(const float* __restrict__ XEp,
                                                     const float* __restrict__ X1p,
                                                     const __half* __restrict__ Xh,
                                                     const float* __restrict__ Wsp,
                                                     const float* __restrict__ bias,
                                                     __half* __restrict__ Hh, int N)
{
    extern __shared__ float sm[];
    float* sAhi = sm;                       // [row*APAD + k], 128x64
    float* sAlo = sAhi + SA_FLOATS;
    float* sWhi = sAlo + SA_FLOATS;         // [n*APAD + k], 64x64
    float* sWlo = sWhi + WSEG_FLOATS;

    const int tid  = threadIdx.x;
    const int lane = tid & 31;
    const int wid  = tid >> 5;
    const int grp  = lane >> 2;
    const int qid  = lane & 3;
    const int wm   = wid & 3;
    const int wn   = wid >> 2;
    const int row0 = blockIdx.x * 128;

    float c[2][4][4];
    #pragma unroll
    for (int mt = 0; mt < 2; mt++)
        #pragma unroll
        for (int nt = 0; nt < 4; nt++)
            #pragma unroll
            for (int j = 0; j < 4; j++) c[mt][nt][j] = 0.f;

    #pragma unroll
    for (int seg = 0; seg < 3; seg++) {
        const float* Wseg = Wsp + (size_t)seg * 2 * WSEG_FLOATS;

        if (seg > 0) __syncthreads();

        // stage A tile [128 x 64] hi/lo split
        #pragma unroll
        for (int i = tid; i < 2048; i += 256) {
            int r  = i >> 4;
            int k4 = (i & 15) * 4;
            int row = row0 + r;
            float4 v = make_float4(0.f, 0.f, 0.f, 0.f);
            if (row < N) {
                if (seg < 2) {
                    const float* A = (seg == 0) ? XEp : X1p;
                    v = *reinterpret_cast<const float4*>(A + (size_t)row * 64 + k4);
                } else {
                    uint2 hv = *reinterpret_cast<const uint2*>(Xh + (size_t)row * 64 + k4);
                    float2 lo2 = __half22float2(*reinterpret_cast<__half2*>(&hv.x));
                    float2 hi2 = __half22float2(*reinterpret_cast<__half2*>(&hv.y));
                    v = make_float4(lo2.x, lo2.y, hi2.x, hi2.y);
                }
            }
            uint4 hi, lo;
            split_tf32(v.x, hi.x, lo.x);
            split_tf32(v.y, hi.y, lo.y);
            split_tf32(v.z, hi.z, lo.z);
            split_tf32(v.w, hi.w, lo.w);
            *reinterpret_cast<uint4*>(&sAhi[r * APAD + k4]) = hi;
            *reinterpret_cast<uint4*>(&sAlo[r * APAD + k4]) = lo;
        }
        // stage pre-split W: straight float4 copy
        #pragma unroll
        for (int i = tid; i < 2176; i += 256) {
            float4 v = __ldg(reinterpret_cast<const float4*>(Wseg) + i);
            *reinterpret_cast<float4*>(&sWhi[i * 4]) = v;
        }
        __syncthreads();

        #pragma unroll
        for (int kst = 0; kst < 8; kst++) {
            const int k0 = kst * 8;

            uint32_t ahi[2][4], alo[2][4];
            #pragma unroll
            for (int mt = 0; mt < 2; mt++) {
                int r0 = (wm * 32 + mt * 16 + grp) * APAD + k0 + qid;
                int r1 = r0 + 8 * APAD;
                ahi[mt][0] = __float_as_uint(sAhi[r0]);
                ahi[mt][1] = __float_as_uint(sAhi[r1]);
                ahi[mt][2] = __float_as_uint(sAhi[r0 + 4]);
                ahi[mt][3] = __float_as_uint(sAhi[r1 + 4]);
                alo[mt][0] = __float_as_uint(sAlo[r0]);
                alo[mt][1] = __float_as_uint(sAlo[r1]);
                alo[mt][2] = __float_as_uint(sAlo[r0 + 4]);
                alo[mt][3] = __float_as_uint(sAlo[r1 + 4]);
            }
            uint32_t bhi[4][2], blo[4][2];
            #pragma unroll
            for (int nt = 0; nt < 4; nt++) {
                int b0 = (wn * 32 + nt * 8 + grp) * APAD + k0 + qid;
                bhi[nt][0] = __float_as_uint(sWhi[b0]);
                bhi[nt][1] = __float_as_uint(sWhi[b0 + 4]);
                blo[nt][0] = __float_as_uint(sWlo[b0]);
                blo[nt][1] = __float_as_uint(sWlo[b0 + 4]);
            }

            #pragma unroll
            for (int mt = 0; mt < 2; mt++) {
                #pragma unroll
                for (int nt = 0; nt < 4; nt++) {
                    mma_tf32(c[mt][nt], ahi[mt], bhi[nt]);
                    mma_tf32(c[mt][nt], alo[mt], bhi[nt]);
                    mma_tf32(c[mt][nt], ahi[mt], blo[nt]);
                }
            }
        }
    }

    // epilogue: bias + relu + fp16 store
    #pragma unroll
    for (int mt = 0; mt < 2; mt++) {
        int rbase = row0 + wm * 32 + mt * 16 + grp;
        #pragma unroll
        for (int nt = 0; nt < 4; nt++) {
            int col = wn * 32 + nt * 8 + 2 * qid;
            float2 b2 = __ldg(reinterpret_cast<const float2*>(bias + col));
            if (rbase < N) {
                float2 v = make_float2(fmaxf(c[mt][nt][0] + b2.x, 0.f),
                                       fmaxf(c[mt][nt][1] + b2.y, 0.f));
                *reinterpret_cast<__half2*>(Hh + (size_t)rbase * 64 + col) = __float22half2_rn(v);
            }
            if (rbase + 8 < N) {
                float2 v = make_float2(fmaxf(c[mt][nt][2] + b2.x, 0.f),
                                       fmaxf(c[mt][nt][3] + b2.y, 0.f));
                *reinterpret_cast<__half2*>(Hh + (size_t)(rbase + 8) * 64 + col) = __float22half2_rn(v);
            }
        }
    }
}

// =================================================================
// Layer 3 fully fused, fp16 gather: warp-per-node gather + 64->4
// projection + butterfly reduce + log_softmax
// =================================================================
__global__ __launch_bounds__(256) void agg3_ls(const int* __restrict__ off,
                                               const int2* __restrict__ meta,
                                               const __half* __restrict__ HBh,
                                               const float* __restrict__ Wm,
                                               const float* __restrict__ Bm,
                                               const float* __restrict__ Wr,
                                               const float* __restrict__ b,
                                               float* __restrict__ OUT, int N)
{
    __shared__ float sw[768];
    int tid = threadIdx.x;
    if (tid < 256) { sw[tid] = Wm[tid]; sw[256 + tid] = Bm[tid]; sw[512 + tid] = Wr[tid]; }
    __syncthreads();

    int w = (blockIdx.x * blockDim.x + tid) >> 5;
    int lane = tid & 31;
    if (w >= N) return;

    int beg = __ldg(off + w);
    int end = __ldg(off + w + 1);

    float2 aE = make_float2(0.f, 0.f);
    float2 a1 = make_float2(0.f, 0.f);

    const __half2* X2 = reinterpret_cast<const __half2*>(HBh);

    int k = beg;
    for (; k + 2 <= end; k += 2) {
        int2 m0 = __ldg(meta + k);
        int2 m1 = __ldg(meta + k + 1);
        float2 v0 = __half22float2(X2[(size_t)m0.x * 32 + lane]);
        float2 v1 = __half22float2(X2[(size_t)m1.x * 32 + lane]);
        float e0 = __int_as_float(m0.y);
        float e1 = __int_as_float(m1.y);
        aE.x = fmaf(e0, v0.x, aE.x); aE.y = fmaf(e0, v0.y, aE.y);
        aE.x = fmaf(e1, v1.x, aE.x); aE.y = fmaf(e1, v1.y, aE.y);
        a1.x += v0.x + v1.x;         a1.y += v0.y + v1.y;
    }
    if (k < end) {
        int2 m0 = __ldg(meta + k);
        float2 v0 = __half22float2(X2[(size_t)m0.x * 32 + lane]);
        float e0 = __int_as_float(m0.y);
        aE.x = fmaf(e0, v0.x, aE.x); aE.y = fmaf(e0, v0.y, aE.y);
        a1.x += v0.x;                a1.y += v0.y;
    }

    float2 hb = __half22float2(X2[(size_t)w * 32 + lane]);

    const int k0 = lane * 2 * 4;
    float p[4];
    #pragma unroll
    for (int c = 0; c < 4; c++) {
        float v = aE.x * sw[k0 + c] + aE.y * sw[k0 + 4 + c];
        v = fmaf(a1.x, sw[256 + k0 + c], v);
        v = fmaf(a1.y, sw[256 + k0 + 4 + c], v);
        v = fmaf(hb.x, sw[512 + k0 + c], v);
        v = fmaf(hb.y, sw[512 + k0 + 4 + c], v);
        p[c] = v;
    }
    #pragma unroll
    for (int d = 16; d > 0; d >>= 1) {
        p[0] += __shfl_xor_sync(0xFFFFFFFFu, p[0], d);
        p[1] += __shfl_xor_sync(0xFFFFFFFFu, p[1], d);
        p[2] += __shfl_xor_sync(0xFFFFFFFFu, p[2], d);
        p[3] += __shfl_xor_sync(0xFFFFFFFFu, p[3], d);
    }

    if (lane == 0) {
        #pragma unroll
        for (int c = 0; c < 4; c++) p[c] += __ldg(b + c);
        float m = fmaxf(fmaxf(p[0], p[1]), fmaxf(p[2], p[3]));
        float s = __expf(p[0] - m) + __expf(p[1] - m) +
                  __expf(p[2] - m) + __expf(p[3] - m);
        float lse = m + __logf(s);
        float4 o;
        o.x = p[0] - lse; o.y = p[1] - lse; o.z = p[2] - lse; o.w = p[3] - lse;
        *reinterpret_cast<float4*>(OUT + (size_t)w * 4) = o;
    }
}

// =================================================================
extern "C" void kernel_launch(void* const* d_in, const int* in_sizes, int n_in,
                              void* d_out, int out_size)
{
    const float* x   = (const float*)d_in[0];
    const int*   ei  = (const int*)  d_in[1];
    const float* ea  = (const float*)d_in[2];
    const float* We1 = (const float*)d_in[3];
    const float* be1 = (const float*)d_in[4];
    const float* Wr1 = (const float*)d_in[5];
    const float* b1  = (const float*)d_in[6];
    const float* We2 = (const float*)d_in[7];
    const float* be2 = (const float*)d_in[8];
    const float* Wr2 = (const float*)d_in[9];
    const float* b2  = (const float*)d_in[10];
    const float* We3 = (const float*)d_in[11];
    const float* be3 = (const float*)d_in[12];
    const float* Wr3 = (const float*)d_in[13];
    const float* b3  = (const float*)d_in[14];

    const int N = in_sizes[0] / DIN;
    const int E = in_sizes[2];

    float *XE, *X1, *Wsp, *OUT = (float*)d_out;
    __half *Xh, *HAh, *HBh;
    int *counts, *off, *cursor, *bsum, *boff;
    int2 *meta;
    cudaGetSymbolAddress((void**)&XE, g_XE);
    cudaGetSymbolAddress((void**)&X1, g_X1);
    cudaGetSymbolAddress((void**)&Xh, g_Xh);
    cudaGetSymbolAddress((void**)&HAh, g_HAh);
    cudaGetSymbolAddress((void**)&HBh, g_HBh);
    cudaGetSymbolAddress((void**)&Wsp, g_Wsp);
    cudaGetSymbolAddress((void**)&counts, g_counts);
    cudaGetSymbolAddress((void**)&off, g_off);
    cudaGetSymbolAddress((void**)&cursor, g_cursor);
    cudaGetSymbolAddress((void**)&bsum, g_bsum);
    cudaGetSymbolAddress((void**)&boff, g_boff);
    cudaGetSymbolAddress((void**)&meta, g_meta);

    cudaFuncSetAttribute(gemm192_tc, cudaFuncAttributeMaxDynamicSharedMemorySize, TC_SMEM_BYTES);

    const int edgeGrid = (E + 255) / 256;
    const int rowGrid  = (N + 255) / 256;
    const int aggGrid  = (N * 32 + 255) / 256;
    const int tcGrid   = (N + 127) / 128;
    const int scanGrid = (N + 2047) / 2048;
    const int cvtGrid  = (N * 64 / 8 + 255) / 256;

    // ---- CSR build + weight pre-split + x->fp16 ----
    zero_kernel<<<rowGrid, 256>>>(counts, N);
    hist_kernel<<<edgeGrid, 256>>>(ei, counts, E);
    scanA_kernel<<<scanGrid, 256>>>(counts, bsum, N);
    scanB_kernel<<<1, 64>>>(bsum, boff, off, scanGrid, N);
    scanC_kernel<<<scanGrid, 256>>>(counts, boff, off, cursor, N);
    scatter_kernel<<<edgeGrid, 256>>>(ei, ea, cursor, meta, E);
    presplit_kernel<<<144, 256>>>(We1, be1, Wr1, We2, be2, Wr2, We3, be3, Wr3, Wsp);
    cvt_half_kernel<<<cvtGrid, 256>>>(x, Xh, N * 64);

    // ---- layer 1 ----
    aggx_h_kernel<<<aggGrid, 256>>>(off, meta, Xh, XE, X1, N);
    gemm192_tc<<<tcGrid, 256, TC_SMEM_BYTES>>>(XE, X1, Xh, Wsp, b1, HAh, N);

    // ---- layer 2 ----
    aggx_h_kernel<<<aggGrid, 256>>>(off, meta, HAh, XE, X1, N);
    gemm192_tc<<<tcGrid, 256, TC_SMEM_BYTES>>>(XE, X1, HAh,
                                               Wsp + (size_t)3 * 2 * WSEG_FLOATS, b2, HBh, N);

    // ---- layer 3 (fully fused) ----
    agg3_ls<<<aggGrid, 256>>>(off, meta, HBh, We3, be3, Wr3, b3, OUT, N);
}

// round 11
// speedup vs baseline: 2.1247x; 1.1205x over previous
#include <cuda_runtime.h>
#include <cuda_fp16.h>
#include <cstdint>

#define MAXN 100000
#define MAXE 1600000
#define DIN  64

// ---------------- scratch (no cudaMalloc allowed) ----------------
__device__ __half g_XEh[(size_t)MAXN * 64];  // sum of e * X[src] per dst (fp16)
__device__ __half g_X1h[(size_t)MAXN * 64];  // sum of X[src] per dst (fp16)
__device__ __half g_Xh[(size_t)MAXN * 64];   // fp16 copy of input x
__device__ __half g_HAh[(size_t)MAXN * 64];  // relu(layer1 out), fp16
__device__ __half g_HBh[(size_t)MAXN * 64];  // relu(layer2 out), fp16
__device__ int    g_counts[MAXN];
__device__ int    g_off[MAXN + 1];
__device__ int    g_cursor[MAXN];
__device__ int    g_bsum[64];
__device__ int    g_boff[64];
__device__ int2   g_meta[MAXE];              // {src, bits(e)} grouped by dst

// pre-split tf32 weights: [mat 0..8][hi/lo][n*68+k]
#define APAD 68
#define WSEG_FLOATS (64 * APAD)              /* 4352 */
__device__ float g_Wsp[9 * 2 * WSEG_FLOATS];

// =================================================================
// CSR build
// =================================================================
__global__ void zero_kernel(int* __restrict__ counts, int N)
{
    int i = blockIdx.x * blockDim.x + threadIdx.x;
    if (i < N) counts[i] = 0;
}

// 4 edges per thread, vectorized dst reads
__global__ void hist_kernel(const int* __restrict__ ei, int* __restrict__ counts, int E)
{
    int i = blockIdx.x * blockDim.x + threadIdx.x;
    int base = i * 4;
    if (base >= E) return;
    if (((E & 3) == 0) && (base + 4 <= E)) {
        int4 d = *reinterpret_cast<const int4*>(ei + E + base);
        atomicAdd(&counts[d.x], 1);
        atomicAdd(&counts[d.y], 1);
        atomicAdd(&counts[d.z], 1);
        atomicAdd(&counts[d.w], 1);
    } else {
        int hi = min(base + 4, E);
        for (int e = base; e < hi; e++) atomicAdd(&counts[__ldg(ei + E + e)], 1);
    }
}

__global__ __launch_bounds__(256) void scanA_kernel(const int* __restrict__ counts,
                                                    int* __restrict__ bsum, int N)
{
    __shared__ int red[256];
    int tid = threadIdx.x;
    int base = blockIdx.x * 2048 + tid * 8;
    int s = 0;
    if (base < N) {
        int4 a = *reinterpret_cast<const int4*>(counts + base);
        int4 b = *reinterpret_cast<const int4*>(counts + base + 4);
        s = a.x + a.y + a.z + a.w + b.x + b.y + b.z + b.w;
    }
    red[tid] = s;
    __syncthreads();
    #pragma unroll
    for (int d = 128; d > 0; d >>= 1) {
        if (tid < d) red[tid] += red[tid + d];
        __syncthreads();
    }
    if (tid == 0) bsum[blockIdx.x] = red[0];
}

__global__ __launch_bounds__(64) void scanB_kernel(const int* __restrict__ bsum,
                                                   int* __restrict__ boff,
                                                   int* __restrict__ off, int B, int N)
{
    __shared__ int sh[64];
    int tid = threadIdx.x;
    int v = (tid < B) ? bsum[tid] : 0;
    sh[tid] = v;
    __syncthreads();
    #pragma unroll
    for (int d = 1; d < 64; d <<= 1) {
        int t = (tid >= d) ? sh[tid - d] : 0;
        __syncthreads();
        sh[tid] += t;
        __syncthreads();
    }
    boff[tid] = sh[tid] - v;
    if (tid == 63) off[N] = sh[63];
}

__global__ __launch_bounds__(256) void scanC_kernel(const int* __restrict__ counts,
                                                    const int* __restrict__ boff,
                                                    int* __restrict__ off,
                                                    int* __restrict__ cursor, int N)
{
    __shared__ int wsum[8], woff[8];
    int tid = threadIdx.x;
    int lane = tid & 31;
    int warp = tid >> 5;
    int base = blockIdx.x * 2048 + tid * 8;

    int4 a = make_int4(0, 0, 0, 0), b = make_int4(0, 0, 0, 0);
    if (base < N) {
        a = *reinterpret_cast<const int4*>(counts + base);
        b = *reinterpret_cast<const int4*>(counts + base + 4);
    }
    int s = a.x + a.y + a.z + a.w + b.x + b.y + b.z + b.w;

    int incl = s;
    #pragma unroll
    for (int d = 1; d < 32; d <<= 1) {
        int t = __shfl_up_sync(0xFFFFFFFFu, incl, d);
        if (lane >= d) incl += t;
    }
    if (lane == 31) wsum[warp] = incl;
    __syncthreads();
    if (tid == 0) {
        int run = 0;
        #pragma unroll
        for (int j = 0; j < 8; j++) { int t = wsum[j]; woff[j] = run; run += t; }
    }
    __syncthreads();

    int ex = __ldg(boff + blockIdx.x) + woff[warp] + (incl - s);
    if (base < N) {
        int o0 = ex;
        int o1 = o0 + a.x, o2 = o1 + a.y, o3 = o2 + a.z, o4 = o3 + a.w;
        int o5 = o4 + b.x, o6 = o5 + b.y, o7 = o6 + b.z;
        int4 oa = make_int4(o0, o1, o2, o3);
        int4 ob = make_int4(o4, o5, o6, o7);
        *reinterpret_cast<int4*>(off + base)        = oa;
        *reinterpret_cast<int4*>(off + base + 4)    = ob;
        *reinterpret_cast<int4*>(cursor + base)     = oa;
        *reinterpret_cast<int4*>(cursor + base + 4) = ob;
    }
}

// 4 edges per thread, vectorized src/dst/ea reads
__global__ void scatter_kernel(const int* __restrict__ ei, const float* __restrict__ ea,
                               int* __restrict__ cursor, int2* __restrict__ meta, int E)
{
    int i = blockIdx.x * blockDim.x + threadIdx.x;
    int base = i * 4;
    if (base >= E) return;
    if (((E & 3) == 0) && (base + 4 <= E)) {
        int4 s4 = *reinterpret_cast<const int4*>(ei + base);
        int4 d4 = *reinterpret_cast<const int4*>(ei + E + base);
        float4 e4 = *reinterpret_cast<const float4*>(ea + base);
        int p0 = atomicAdd(&cursor[d4.x], 1);
        int p1 = atomicAdd(&cursor[d4.y], 1);
        int p2 = atomicAdd(&cursor[d4.z], 1);
        int p3 = atomicAdd(&cursor[d4.w], 1);
        meta[p0] = make_int2(s4.x, __float_as_int(e4.x));
        meta[p1] = make_int2(s4.y, __float_as_int(e4.y));
        meta[p2] = make_int2(s4.z, __float_as_int(e4.z));
        meta[p3] = make_int2(s4.w, __float_as_int(e4.w));
    } else {
        int hi = min(base + 4, E);
        for (int e = base; e < hi; e++) {
            int s = __ldg(ei + e);
            int d = __ldg(ei + E + e);
            int pos = atomicAdd(&cursor[d], 1);
            meta[pos] = make_int2(s, __float_as_int(__ldg(ea + e)));
        }
    }
}

// =================================================================
// tf32 split + weight pre-split (unchanged)
// =================================================================
__device__ __forceinline__ void split_tf32(float v, uint32_t& hi, uint32_t& lo)
{
    asm("cvt.rna.tf32.f32 %0, %1;" : "=r"(hi) : "f"(v));
    float r = v - __uint_as_float(hi);
    asm("cvt.rna.tf32.f32 %0, %1;" : "=r"(lo) : "f"(r));
}

__global__ __launch_bounds__(256) void presplit_kernel(
    const float* __restrict__ m0, const float* __restrict__ m1, const float* __restrict__ m2,
    const float* __restrict__ m3, const float* __restrict__ m4, const float* __restrict__ m5,
    const float* __restrict__ m6, const float* __restrict__ m7, const float* __restrict__ m8,
    float* __restrict__ out)
{
    int idx = blockIdx.x * blockDim.x + threadIdx.x;
    if (idx >= 9 * 4096) return;
    int mat = idx >> 12;
    int j = idx & 4095;
    int k = j >> 6;
    int n = j & 63;

    const float* src;
    switch (mat) {
        case 0: src = m0; break; case 1: src = m1; break; case 2: src = m2; break;
        case 3: src = m3; break; case 4: src = m4; break; case 5: src = m5; break;
        case 6: src = m6; break; case 7: src = m7; break; default: src = m8; break;
    }
    uint32_t hi, lo;
    split_tf32(__ldg(src + j), hi, lo);
    float* dst = out + (size_t)mat * 2 * WSEG_FLOATS;
    dst[n * APAD + k]               = __uint_as_float(hi);
    dst[WSEG_FLOATS + n * APAD + k] = __uint_as_float(lo);
}

// =================================================================
// x -> fp16 conversion (one-time)
// =================================================================
__global__ __launch_bounds__(256) void cvt_half_kernel(const float* __restrict__ X,
                                                       __half* __restrict__ Xh, int total)
{
    int i = blockIdx.x * blockDim.x + threadIdx.x;
    int base = i * 8;
    if (base >= total) return;
    float4 a = *reinterpret_cast<const float4*>(X + base);
    float4 b = *reinterpret_cast<const float4*>(X + base + 4);
    __half2 h[4];
    h[0] = __float22half2_rn(make_float2(a.x, a.y));
    h[1] = __float22half2_rn(make_float2(a.z, a.w));
    h[2] = __float22half2_rn(make_float2(b.x, b.y));
    h[3] = __float22half2_rn(make_float2(b.z, b.w));
    *reinterpret_cast<uint4*>(Xh + base) = *reinterpret_cast<uint4*>(h);
}

// =================================================================
// fp16-gather aggregation -> fp16 outputs
// =================================================================
__global__ __launch_bounds__(256) void aggx_h_kernel(const int* __restrict__ off,
                                                     const int2* __restrict__ meta,
                                                     const __half* __restrict__ Xh,
                                                     __half* __restrict__ XEh,
                                                     __half* __restrict__ X1h, int N)
{
    int w = (blockIdx.x * blockDim.x + threadIdx.x) >> 5;
    int lane = threadIdx.x & 31;
    if (w >= N) return;

    int beg = __ldg(off + w);
    int end = __ldg(off + w + 1);

    float2 aE = make_float2(0.f, 0.f);
    float2 a1 = make_float2(0.f, 0.f);

    const __half2* X2 = reinterpret_cast<const __half2*>(Xh);

    int k = beg;
    for (; k + 2 <= end; k += 2) {
        int2 m0 = __ldg(meta + k);
        int2 m1 = __ldg(meta + k + 1);
        float2 v0 = __half22float2(X2[(size_t)m0.x * 32 + lane]);
        float2 v1 = __half22float2(X2[(size_t)m1.x * 32 + lane]);
        float e0 = __int_as_float(m0.y);
        float e1 = __int_as_float(m1.y);
        aE.x = fmaf(e0, v0.x, aE.x); aE.y = fmaf(e0, v0.y, aE.y);
        aE.x = fmaf(e1, v1.x, aE.x); aE.y = fmaf(e1, v1.y, aE.y);
        a1.x += v0.x + v1.x;         a1.y += v0.y + v1.y;
    }
    if (k < end) {
        int2 m0 = __ldg(meta + k);
        float2 v0 = __half22float2(X2[(size_t)m0.x * 32 + lane]);
        float e0 = __int_as_float(m0.y);
        aE.x = fmaf(e0, v0.x, aE.x); aE.y = fmaf(e0, v0.y, aE.y);
        a1.x += v0.x;                a1.y += v0.y;
    }

    reinterpret_cast<__half2*>(XEh)[(size_t)w * 32 + lane] = __float22half2_rn(aE);
    reinterpret_cast<__half2*>(X1h)[(size_t)w * 32 + lane] = __float22half2_rn(a1);
}

// =================================================================
// TF32 tensor-core GEMM, all-fp16 A (exactly tf32-representable =>
// A lo-term is zero => 2 MMAs per k-step): H = relu(...)
// smem = A(hi only) + W(hi/lo) = 69632 B => 3 CTAs/SM
// =================================================================
#define SA_FLOATS (128 * APAD)     /* 8704 */
#define TC_SMEM_FLOATS (SA_FLOATS + 2 * WSEG_FLOATS)
#define TC_SMEM_BYTES  (TC_SMEM_FLOATS * 4)   /* 69632 B */

__device__ __forceinline__ void mma_tf32(float* c, const uint32_t* a, const uint32_t* b)
{
    asm("mma.sync.aligned.m16n8k8.row.col.f32.tf32.tf32.f32 "
        "{%0,%1,%2,%3}, {%4,%5,%6,%7}, {%8,%9}, {%0,%1,%2,%3};"
        : "+f"(c[0]), "+f"(c[1]), "+f"(c[2]), "+f"(c[3])
        : "r"(a[0]), "r"(a[1]), "r"(a[2]), "r"(a[3]), "r"(b[0]), "r"(b[1]));
}

__global__ __launch_bounds__(256, 3) void gemm192_tc(const __half* __restrict__ XEh,
                                                     const __half* __restrict__ X1h,
                                                     const __half* __restrict__ Xh,
                                                     const float* __restrict__ Wsp,
                                                     const float* __restrict__ bias,
                                                     __half* __restrict__ Hh, int N)
{
    extern __shared__ float sm[];
    float* sA   = sm;                       // [row*APAD + k], 128x64 (tf32-exact)
    float* sWhi = sm + SA_FLOATS;           // [n*APAD + k], hi then lo contiguous
    float* sWlo = sWhi + WSEG_FLOATS;

    const int tid  = threadIdx.x;
    const int lane = tid & 31;
    const int wid  = tid >> 5;
    const int grp  = lane >> 2;
    const int qid  = lane & 3;
    const int wm   = wid & 3;
    const int wn   = wid >> 2;
    const int row0 = blockIdx.x * 128;

    float c[2][4][4];
    #pragma unroll
    for (int mt = 0; mt < 2; mt++)
        #pragma unroll
        for (int nt = 0; nt < 4; nt++)
            #pragma unroll
            for (int j = 0; j < 4; j++) c[mt][nt][j] = 0.f;

    #pragma unroll
    for (int seg = 0; seg < 3; seg++) {
        const __half* A = (seg == 0) ? XEh : (seg == 1) ? X1h : Xh;
        const float* Wseg = Wsp + (size_t)seg * 2 * WSEG_FLOATS;

        if (seg > 0) __syncthreads();

        // stage A tile [128 x 64]: fp16 -> f32 (exact; valid tf32 operands)
        #pragma unroll
        for (int i = tid; i < 2048; i += 256) {
            int r  = i >> 4;
            int k4 = (i & 15) * 4;
            int row = row0 + r;
            float4 v = make_float4(0.f, 0.f, 0.f, 0.f);
            if (row < N) {
                uint2 hv = *reinterpret_cast<const uint2*>(A + (size_t)row * 64 + k4);
                float2 lo2 = __half22float2(*reinterpret_cast<__half2*>(&hv.x));
                float2 hi2 = __half22float2(*reinterpret_cast<__half2*>(&hv.y));
                v = make_float4(lo2.x, lo2.y, hi2.x, hi2.y);
            }
            *reinterpret_cast<float4*>(&sA[r * APAD + k4]) = v;
        }
        // stage pre-split W (hi+lo): straight float4 copy
        #pragma unroll
        for (int i = tid; i < 2176; i += 256) {
            float4 v = __ldg(reinterpret_cast<const float4*>(Wseg) + i);
            *reinterpret_cast<float4*>(&sWhi[i * 4]) = v;
        }
        __syncthreads();

        #pragma unroll
        for (int kst = 0; kst < 8; kst++) {
            const int k0 = kst * 8;

            uint32_t a[2][4];
            #pragma unroll
            for (int mt = 0; mt < 2; mt++) {
                int r0 = (wm * 32 + mt * 16 + grp) * APAD + k0 + qid;
                int r1 = r0 + 8 * APAD;
                a[mt][0] = __float_as_uint(sA[r0]);
                a[mt][1] = __float_as_uint(sA[r1]);
                a[mt][2] = __float_as_uint(sA[r0 + 4]);
                a[mt][3] = __float_as_uint(sA[r1 + 4]);
            }
            uint32_t bhi[4][2], blo[4][2];
            #pragma unroll
            for (int nt = 0; nt < 4; nt++) {
                int b0 = (wn * 32 + nt * 8 + grp) * APAD + k0 + qid;
                bhi[nt][0] = __float_as_uint(sWhi[b0]);
                bhi[nt][1] = __float_as_uint(sWhi[b0 + 4]);
                blo[nt][0] = __float_as_uint(sWlo[b0]);
                blo[nt][1] = __float_as_uint(sWlo[b0 + 4]);
            }

            #pragma unroll
            for (int mt = 0; mt < 2; mt++) {
                #pragma unroll
                for (int nt = 0; nt < 4; nt++) {
                    mma_tf32(c[mt][nt], a[mt], bhi[nt]);
                    mma_tf32(c[mt][nt], a[mt], blo[nt]);
                }
            }
        }
    }

    // epilogue: bias + relu + fp16 store
    #pragma unroll
    for (int mt = 0; mt < 2; mt++) {
        int rbase = row0 + wm * 32 + mt * 16 + grp;
        #pragma unroll
        for (int nt = 0; nt < 4; nt++) {
            int col = wn * 32 + nt * 8 + 2 * qid;
            float2 b2 = __ldg(reinterpret_cast<const float2*>(bias + col));
            if (rbase < N) {
                float2 v = make_float2(fmaxf(c[mt][nt][0] + b2.x, 0.f),
                                       fmaxf(c[mt][nt][1] + b2.y, 0.f));
                *reinterpret_cast<__half2*>(Hh + (size_t)rbase * 64 + col) = __float22half2_rn(v);
            }
            if (rbase + 8 < N) {
                float2 v = make_float2(fmaxf(c[mt][nt][2] + b2.x, 0.f),
                                       fmaxf(c[mt][nt][3] + b2.y, 0.f));
                *reinterpret_cast<__half2*>(Hh + (size_t)(rbase + 8) * 64 + col) = __float22half2_rn(v);
            }
        }
    }
}

// =================================================================
// Layer 3 fully fused (unchanged from R10)
// =================================================================
__global__ __launch_bounds__(256) void agg3_ls(const int* __restrict__ off,
                                               const int2* __restrict__ meta,
                                               const __half* __restrict__ HBh,
                                               const float* __restrict__ Wm,
                                               const float* __restrict__ Bm,
                                               const float* __restrict__ Wr,
                                               const float* __restrict__ b,
                                               float* __restrict__ OUT, int N)
{
    __shared__ float sw[768];
    int tid = threadIdx.x;
    if (tid < 256) { sw[tid] = Wm[tid]; sw[256 + tid] = Bm[tid]; sw[512 + tid] = Wr[tid]; }
    __syncthreads();

    int w = (blockIdx.x * blockDim.x + tid) >> 5;
    int lane = tid & 31;
    if (w >= N) return;

    int beg = __ldg(off + w);
    int end = __ldg(off + w + 1);

    float2 aE = make_float2(0.f, 0.f);
    float2 a1 = make_float2(0.f, 0.f);

    const __half2* X2 = reinterpret_cast<const __half2*>(HBh);

    int k = beg;
    for (; k + 2 <= end; k += 2) {
        int2 m0 = __ldg(meta + k);
        int2 m1 = __ldg(meta + k + 1);
        float2 v0 = __half22float2(X2[(size_t)m0.x * 32 + lane]);
        float2 v1 = __half22float2(X2[(size_t)m1.x * 32 + lane]);
        float e0 = __int_as_float(m0.y);
        float e1 = __int_as_float(m1.y);
        aE.x = fmaf(e0, v0.x, aE.x); aE.y = fmaf(e0, v0.y, aE.y);
        aE.x = fmaf(e1, v1.x, aE.x); aE.y = fmaf(e1, v1.y, aE.y);
        a1.x += v0.x + v1.x;         a1.y += v0.y + v1.y;
    }
    if (k < end) {
        int2 m0 = __ldg(meta + k);
        float2 v0 = __half22float2(X2[(size_t)m0.x * 32 + lane]);
        float e0 = __int_as_float(m0.y);
        aE.x = fmaf(e0, v0.x, aE.x); aE.y = fmaf(e0, v0.y, aE.y);
        a1.x += v0.x;                a1.y += v0.y;
    }

    float2 hb = __half22float2(X2[(size_t)w * 32 + lane]);

    const int k0 = lane * 2 * 4;
    float p[4];
    #pragma unroll
    for (int c = 0; c < 4; c++) {
        float v = aE.x * sw[k0 + c] + aE.y * sw[k0 + 4 + c];
        v = fmaf(a1.x, sw[256 + k0 + c], v);
        v = fmaf(a1.y, sw[256 + k0 + 4 + c], v);
        v = fmaf(hb.x, sw[512 + k0 + c], v);
        v = fmaf(hb.y, sw[512 + k0 + 4 + c], v);
        p[c] = v;
    }
    #pragma unroll
    for (int d = 16; d > 0; d >>= 1) {
        p[0] += __shfl_xor_sync(0xFFFFFFFFu, p[0], d);
        p[1] += __shfl_xor_sync(0xFFFFFFFFu, p[1], d);
        p[2] += __shfl_xor_sync(0xFFFFFFFFu, p[2], d);
        p[3] += __shfl_xor_sync(0xFFFFFFFFu, p[3], d);
    }

    if (lane == 0) {
        #pragma unroll
        for (int c = 0; c < 4; c++) p[c] += __ldg(b + c);
        float m = fmaxf(fmaxf(p[0], p[1]), fmaxf(p[2], p[3]));
        float s = __expf(p[0] - m) + __expf(p[1] - m) +
                  __expf(p[2] - m) + __expf(p[3] - m);
        float lse = m + __logf(s);
        float4 o;
        o.x = p[0] - lse; o.y = p[1] - lse; o.z = p[2] - lse; o.w = p[3] - lse;
        *reinterpret_cast<float4*>(OUT + (size_t)w * 4) = o;
    }
}

// =================================================================
extern "C" void kernel_launch(void* const* d_in, const int* in_sizes, int n_in,
                              void* d_out, int out_size)
{
    const float* x   = (const float*)d_in[0];
    const int*   ei  = (const int*)  d_in[1];
    const float* ea  = (const float*)d_in[2];
    const float* We1 = (const float*)d_in[3];
    const float* be1 = (const float*)d_in[4];
    const float* Wr1 = (const float*)d_in[5];
    const float* b1  = (const float*)d_in[6];
    const float* We2 = (const float*)d_in[7];
    const float* be2 = (const float*)d_in[8];
    const float* Wr2 = (const float*)d_in[9];
    const float* b2  = (const float*)d_in[10];
    const float* We3 = (const float*)d_in[11];
    const float* be3 = (const float*)d_in[12];
    const float* Wr3 = (const float*)d_in[13];
    const float* b3  = (const float*)d_in[14];

    const int N = in_sizes[0] / DIN;
    const int E = in_sizes[2];

    float *Wsp, *OUT = (float*)d_out;
    __half *XEh, *X1h, *Xh, *HAh, *HBh;
    int *counts, *off, *cursor, *bsum, *boff;
    int2 *meta;
    cudaGetSymbolAddress((void**)&XEh, g_XEh);
    cudaGetSymbolAddress((void**)&X1h, g_X1h);
    cudaGetSymbolAddress((void**)&Xh, g_Xh);
    cudaGetSymbolAddress((void**)&HAh, g_HAh);
    cudaGetSymbolAddress((void**)&HBh, g_HBh);
    cudaGetSymbolAddress((void**)&Wsp, g_Wsp);
    cudaGetSymbolAddress((void**)&counts, g_counts);
    cudaGetSymbolAddress((void**)&off, g_off);
    cudaGetSymbolAddress((void**)&cursor, g_cursor);
    cudaGetSymbolAddress((void**)&bsum, g_bsum);
    cudaGetSymbolAddress((void**)&boff, g_boff);
    cudaGetSymbolAddress((void**)&meta, g_meta);

    cudaFuncSetAttribute(gemm192_tc, cudaFuncAttributeMaxDynamicSharedMemorySize, TC_SMEM_BYTES);

    const int edge4Grid = (E / 4 + 256) / 256;
    const int rowGrid   = (N + 255) / 256;
    const int aggGrid   = (N * 32 + 255) / 256;
    const int tcGrid    = (N + 127) / 128;
    const int scanGrid  = (N + 2047) / 2048;
    const int cvtGrid   = (N * 64 / 8 + 255) / 256;

    // ---- CSR build + weight pre-split + x->fp16 ----
    zero_kernel<<<rowGrid, 256>>>(counts, N);
    hist_kernel<<<edge4Grid, 256>>>(ei, counts, E);
    scanA_kernel<<<scanGrid, 256>>>(counts, bsum, N);
    scanB_kernel<<<1, 64>>>(bsum, boff, off, scanGrid, N);
    scanC_kernel<<<scanGrid, 256>>>(counts, boff, off, cursor, N);
    scatter_kernel<<<edge4Grid, 256>>>(ei, ea, cursor, meta, E);
    presplit_kernel<<<144, 256>>>(We1, be1, Wr1, We2, be2, Wr2, We3, be3, Wr3, Wsp);
    cvt_half_kernel<<<cvtGrid, 256>>>(x, Xh, N * 64);

    // ---- layer 1 ----
    aggx_h_kernel<<<aggGrid, 256>>>(off, meta, Xh, XEh, X1h, N);
    gemm192_tc<<<tcGrid, 256, TC_SMEM_BYTES>>>(XEh, X1h, Xh, Wsp, b1, HAh, N);

    // ---- layer 2 ----
    aggx_h_kernel<<<aggGrid, 256>>>(off, meta, HAh, XEh, X1h, N);
    gemm192_tc<<<tcGrid, 256, TC_SMEM_BYTES>>>(XEh, X1h, HAh,
                                               Wsp + (size_t)3 * 2 * WSEG_FLOATS, b2, HBh, N);

    // ---- layer 3 (fully fused) ----
    agg3_ls<<<aggGrid, 256>>>(off, meta, HBh, We3, be3, Wr3, b3, OUT, N);
}